// round 13
// baseline (speedup 1.0000x reference)
#include <cuda_runtime.h>
#include <math.h>
#include <stdint.h>

#define NB   2
#define CIN  256
#define Hh   96
#define Ww   96
#define HW   9216
#define BC   128
#define C4   512
#define C5   640
#define COUT 256
#define KMASK 4608   // 512*9

#define APITCH 20    // uint2 per A row (16 used + 4 pad); 20 % 16 == 4 -> conflict-free
#define BPITCH 132   // uint2 per B k-row; 132 % 16 == 4 -> conflict-free

#define ASZ (128 * APITCH * 8)          // 20480 B per A buffer
#define BSZ (16  * BPITCH * 8)          // 16896 B per B buffer
#define SMEM_GEMM (2 * (ASZ + BSZ))     // 74752 B (double-buffered)

// ---- scratch (static device arrays; no allocation) ----
__device__ float g_cv1[(size_t)NB*C5*HW];      // conv1x1 out: ch 0..127 = cur, 128..639 = ltrb (post-IN in place)
__device__ float g_f4t[(size_t)NB*4*HW*BC];    // feat4 transposed: [n][border][hw][c]
__device__ float g_ltrb[(size_t)NB*C4*HW];     // border-align output in the reshaped [n][512][HW] layout
__device__ float g_mask[(size_t)NB*C5*HW];     // sigmoid(conv3x3)

__device__ __forceinline__ uint32_t to_tf32(float x) {
    uint32_t y;
    asm("cvt.rna.tf32.f32 %0, %1;" : "=r"(y) : "f"(x));
    return y;
}

__device__ __forceinline__ void mma_tf32(float* c, const uint32_t* a, const uint32_t* b) {
    asm volatile(
        "mma.sync.aligned.m16n8k8.row.col.f32.tf32.tf32.f32 "
        "{%0,%1,%2,%3}, {%4,%5,%6,%7}, {%8,%9}, {%0,%1,%2,%3};"
        : "+f"(c[0]), "+f"(c[1]), "+f"(c[2]), "+f"(c[3])
        : "r"(a[0]), "r"(a[1]), "r"(a[2]), "r"(a[3]), "r"(b[0]), "r"(b[1]));
}

// 4-warp tile compute: warp tile 64(M) x 64(N), block tile 128x128x32.
__device__ __forceinline__ void gemm_tile64(const uint2* As2, const uint2* Bs2,
    float acc[4][8][4], int warp_m, int warp_n, int lr, int lq)
{
#pragma unroll
    for (int ks = 0; ks < 4; ++ks) {
        const int kp = ks * 4 + lq;
        uint32_t afr[4][4], bfr[8][2];
#pragma unroll
        for (int mt = 0; mt < 4; ++mt) {
            int row = warp_m * 64 + mt * 16 + lr;
            uint2 alo = As2[row * APITCH + kp];
            uint2 ahi = As2[(row + 8) * APITCH + kp];
            afr[mt][0] = alo.x; afr[mt][1] = ahi.x;
            afr[mt][2] = alo.y; afr[mt][3] = ahi.y;
        }
#pragma unroll
        for (int nt = 0; nt < 8; ++nt) {
            int col = warp_n * 64 + nt * 8 + lr;
            uint2 b = Bs2[kp * BPITCH + col];
            bfr[nt][0] = b.x; bfr[nt][1] = b.y;
        }
#pragma unroll
        for (int mt = 0; mt < 4; ++mt)
#pragma unroll
            for (int nt = 0; nt < 8; ++nt)
                mma_tf32(acc[mt][nt], afr[mt], bfr[nt]);
    }
}

// ============================================================================
// K1: fused conv1x1 (cur||ltrb) = GEMM [640,256]x[256,HW] + bias, tf32 mma.
// 4 warps, 64x64 warp tile, double-buffered smem, one sync per k-tile.
// ============================================================================
__global__ __launch_bounds__(128) void k_conv1(const float* __restrict__ feat,
    const float* __restrict__ w_cur, const float* __restrict__ b_cur,
    const float* __restrict__ w_ltrb, const float* __restrict__ b_ltrb)
{
    extern __shared__ __align__(16) uint8_t smem_raw[];
    uint2* Abuf[2] = { (uint2*)smem_raw, (uint2*)(smem_raw + ASZ) };
    uint2* Bbuf[2] = { (uint2*)(smem_raw + 2 * ASZ), (uint2*)(smem_raw + 2 * ASZ + BSZ) };

    const int c0  = blockIdx.y * 128;
    const int p0  = blockIdx.x * 128;
    const int n   = p0 / HW;
    const int hw0 = p0 - n * HW;
    const float* X = feat + (size_t)n * CIN * HW + hw0;
    const int tid  = threadIdx.x;
    const int lane = tid & 31;
    const int wid  = tid >> 5;
    const int warp_m = wid & 1;
    const int warp_n = wid >> 1;
    const int lr = lane >> 2;
    const int lq = lane & 3;

    const int am  = tid >> 4;
    const int app = tid & 15;
    const int aklo = ((app >> 2) << 3) + (app & 3);
    const int bcol = tid;

    float acc[4][8][4];
#pragma unroll
    for (int mt = 0; mt < 4; ++mt)
#pragma unroll
        for (int nt = 0; nt < 8; ++nt)
#pragma unroll
            for (int r = 0; r < 4; ++r) acc[mt][nt][r] = 0.f;

    float2 rA[16], rB[16];
    // prologue: stage tile 0 into buffer 0
#pragma unroll
    for (int j = 0; j < 16; ++j) {
        int c = c0 + am + 8 * j;
        const float* W = (c < BC) ? (w_cur + c * CIN) : (w_ltrb + (c - BC) * CIN);
        uint2 v; v.x = to_tf32(W[aklo]); v.y = to_tf32(W[aklo + 4]);
        Abuf[0][(am + 8 * j) * APITCH + app] = v;
    }
#pragma unroll
    for (int pr = 0; pr < 16; ++pr) {
        int klo = ((pr >> 2) << 3) + (pr & 3);
        uint2 v; v.x = to_tf32(X[(size_t)klo * HW + bcol]);
        v.y = to_tf32(X[(size_t)(klo + 4) * HW + bcol]);
        Bbuf[0][pr * BPITCH + bcol] = v;
    }
    __syncthreads();

    const int NT = CIN / 32;
    for (int kt = 0; kt < NT; ++kt) {
        const bool more = (kt + 1 < NT);
        if (more) {
            int k0 = (kt + 1) * 32;
#pragma unroll
            for (int j = 0; j < 16; ++j) {
                int c = c0 + am + 8 * j;
                const float* W = (c < BC) ? (w_cur + c * CIN) : (w_ltrb + (c - BC) * CIN);
                rA[j].x = W[k0 + aklo];
                rA[j].y = W[k0 + aklo + 4];
            }
#pragma unroll
            for (int pr = 0; pr < 16; ++pr) {
                int klo = k0 + ((pr >> 2) << 3) + (pr & 3);
                rB[pr].x = X[(size_t)klo * HW + bcol];
                rB[pr].y = X[(size_t)(klo + 4) * HW + bcol];
            }
        }
        gemm_tile64(Abuf[kt & 1], Bbuf[kt & 1], acc, warp_m, warp_n, lr, lq);
        if (more) {
            uint2* An = Abuf[(kt + 1) & 1];
            uint2* Bn = Bbuf[(kt + 1) & 1];
#pragma unroll
            for (int j = 0; j < 16; ++j) {
                uint2 v; v.x = to_tf32(rA[j].x); v.y = to_tf32(rA[j].y);
                An[(am + 8 * j) * APITCH + app] = v;
            }
#pragma unroll
            for (int pr = 0; pr < 16; ++pr) {
                uint2 v; v.x = to_tf32(rB[pr].x); v.y = to_tf32(rB[pr].y);
                Bn[pr * BPITCH + bcol] = v;
            }
        }
        __syncthreads();
    }

#pragma unroll
    for (int mt = 0; mt < 4; ++mt) {
        int c_lo = c0 + warp_m * 64 + mt * 16 + lr;
        int c_hi = c_lo + 8;
        float bias_lo = (c_lo < BC) ? b_cur[c_lo] : b_ltrb[c_lo - BC];
        float bias_hi = (c_hi < BC) ? b_cur[c_hi] : b_ltrb[c_hi - BC];
#pragma unroll
        for (int nt = 0; nt < 8; ++nt) {
            int p = hw0 + warp_n * 64 + nt * 8 + 2 * lq;
            float2 lo, hi;
            lo.x = acc[mt][nt][0] + bias_lo;
            lo.y = acc[mt][nt][1] + bias_lo;
            hi.x = acc[mt][nt][2] + bias_hi;
            hi.y = acc[mt][nt][3] + bias_hi;
            *(float2*)(g_cv1 + ((size_t)n * C5 + c_lo) * HW + p) = lo;
            *(float2*)(g_cv1 + ((size_t)n * C5 + c_hi) * HW + p) = hi;
        }
    }
}

// ============================================================================
// K2: instance norm (biased var, eps=1e-5) + ReLU, in place. One block per (n,c).
// ============================================================================
__global__ __launch_bounds__(256) void k_inorm()
{
    const int nc = blockIdx.x;          // n*C5 + c
    float4* base = (float4*)(g_cv1 + (size_t)nc * HW);
    const int tid = threadIdx.x;
    float s = 0.f, q = 0.f;
#pragma unroll
    for (int i = tid; i < HW / 4; i += 256) {
        float4 v = base[i];
        s += v.x + v.y + v.z + v.w;
        q += v.x * v.x + v.y * v.y + v.z * v.z + v.w * v.w;
    }
    __shared__ float ss[256], qq[256];
    ss[tid] = s; qq[tid] = q;
    __syncthreads();
    for (int off = 128; off > 0; off >>= 1) {
        if (tid < off) { ss[tid] += ss[tid + off]; qq[tid] += qq[tid + off]; }
        __syncthreads();
    }
    const float mean = ss[0] * (1.f / HW);
    const float var  = qq[0] * (1.f / HW) - mean * mean;
    const float rstd = rsqrtf(var + 1e-5f);
#pragma unroll
    for (int i = tid; i < HW / 4; i += 256) {
        float4 v = base[i];
        v.x = fmaxf((v.x - mean) * rstd, 0.f);
        v.y = fmaxf((v.y - mean) * rstd, 0.f);
        v.z = fmaxf((v.z - mean) * rstd, 0.f);
        v.w = fmaxf((v.w - mean) * rstd, 0.f);
        base[i] = v;
    }
}

// ============================================================================
// K2b: transpose feat4 (channels 128..639 of g_cv1) into [n][b][hw][c]
// ============================================================================
__global__ void k_transpose()
{
    __shared__ float t[32][33];
    const int n   = blockIdx.z;
    const int c0  = blockIdx.y * 32;    // 0..511 relative to feat4
    const int hw0 = blockIdx.x * 32;
    const int tx = threadIdx.x, ty = threadIdx.y;   // 32 x 8
    const float* src = g_cv1 + ((size_t)n * C5 + BC + c0) * HW + hw0;
#pragma unroll
    for (int r = 0; r < 4; ++r)
        t[ty + r * 8][tx] = src[(size_t)(ty + r * 8) * HW + tx];
    __syncthreads();
    const int b   = c0 >> 7;
    const int cc0 = c0 & 127;
    float* dst = g_f4t + (((size_t)n * 4 + b) * HW + hw0) * BC + cc0;
#pragma unroll
    for (int r = 0; r < 4; ++r)
        dst[(size_t)(ty + r * 8) * BC + tx] = t[tx][ty + r * 8];
}

// ============================================================================
// K3: BorderAlign. 4 pixels per block; params precomputed to smem; each thread
// handles 4 channels (float4 gathers) for one pixel.
// ============================================================================
struct SampP { int o00, o01, o10, o11; float w00, w01, w10, w11; };

__global__ __launch_bounds__(128) void k_border(const float* __restrict__ boxes)
{
    __shared__ SampP sp[4][44];
    const int blk = blockIdx.x;         // pixel quad
    const int t  = threadIdx.x;

    for (int s = t; s < 176; s += 128) {
        const int pix = s / 44, q = s - pix * 44;
        const int b = q / 11, i = q - b * 11;
        const int P = blk * 4 + pix;
        const int n = P / HW, hw = P - n * HW;
        const float4 bx = *(const float4*)(boxes + ((size_t)n * HW + hw) * 4);
        const float bw = (bx.z - bx.x) * 0.1f, bh = (bx.w - bx.y) * 0.1f;
        const float sx = (b == 3) ? bx.z : bx.x;
        const float sy = (b == 2) ? bx.w : bx.y;
        const float dx = (b == 0 || b == 2) ? bw : 0.f;
        const float dy = (b == 1 || b == 3) ? bh : 0.f;
        const float x = sx + dx * (float)i;
        const float y = sy + dy * (float)i;
        const bool valid = (x >= -1.f) && (x <= 96.f) && (y >= -1.f) && (y <= 96.f);
        const float xc = fminf(fmaxf(x, 0.f), 95.f);
        const float yc = fminf(fmaxf(y, 0.f), 95.f);
        int x0 = (int)floorf(xc); if (x0 > 95) x0 = 95;
        int y0 = (int)floorf(yc); if (y0 > 95) y0 = 95;
        const int x1i = x0 + 1 > 95 ? 95 : x0 + 1;
        const int y1i = y0 + 1 > 95 ? 95 : y0 + 1;
        const float lx = (x0 >= 95) ? 0.f : (xc - (float)x0);
        const float ly = (y0 >= 95) ? 0.f : (yc - (float)y0);
        const float hx = 1.f - lx, hy = 1.f - ly;
        const float sv = valid ? 1.f : 0.f;
        SampP p;
        p.o00 = (y0  * 96 + x0 ) * BC;
        p.o01 = (y0  * 96 + x1i) * BC;
        p.o10 = (y1i * 96 + x0 ) * BC;
        p.o11 = (y1i * 96 + x1i) * BC;
        p.w00 = hy * hx * sv;
        p.w01 = hy * lx * sv;
        p.w10 = ly * hx * sv;
        p.w11 = ly * lx * sv;
        sp[pix][q] = p;
    }
    __syncthreads();

    const int half = t >> 5;            // pixel 0..3
    const int ch   = (t & 31) * 4;      // channel quad
    const int P = blk * 4 + half;
    const int n = P / HW, hw = P - n * HW;
    const float* ftn = g_f4t + (size_t)n * 4 * HW * BC + ch;
    float4 o[4];
#pragma unroll
    for (int b = 0; b < 4; ++b) {
        const float* fb = ftn + b * (HW * BC);
        float m0 = -3.4e38f, m1 = -3.4e38f, m2 = -3.4e38f, m3 = -3.4e38f;
#pragma unroll
        for (int i = 0; i < 11; ++i) {
            const SampP p = sp[half][b * 11 + i];
            const float4 v00 = *(const float4*)(fb + p.o00);
            const float4 v01 = *(const float4*)(fb + p.o01);
            const float4 v10 = *(const float4*)(fb + p.o10);
            const float4 v11 = *(const float4*)(fb + p.o11);
            float a0 = p.w00 * v00.x;
            a0 = fmaf(p.w01, v01.x, a0);
            a0 = fmaf(p.w10, v10.x, a0);
            a0 = fmaf(p.w11, v11.x, a0);
            float a1 = p.w00 * v00.y;
            a1 = fmaf(p.w01, v01.y, a1);
            a1 = fmaf(p.w10, v10.y, a1);
            a1 = fmaf(p.w11, v11.y, a1);
            float a2 = p.w00 * v00.z;
            a2 = fmaf(p.w01, v01.z, a2);
            a2 = fmaf(p.w10, v10.z, a2);
            a2 = fmaf(p.w11, v11.z, a2);
            float a3 = p.w00 * v00.w;
            a3 = fmaf(p.w01, v01.w, a3);
            a3 = fmaf(p.w10, v10.w, a3);
            a3 = fmaf(p.w11, v11.w, a3);
            m0 = fmaxf(m0, a0);
            m1 = fmaxf(m1, a1);
            m2 = fmaxf(m2, a2);
            m3 = fmaxf(m3, a3);
        }
        o[b].x = m0; o[b].y = m1; o[b].z = m2; o[b].w = m3;
    }
    float* base = g_ltrb + (size_t)n * C4 * HW;
    float4 r0; r0.x = o[0].x; r0.y = o[1].x; r0.z = o[2].x; r0.w = o[3].x;
    float4 r1; r1.x = o[0].y; r1.y = o[1].y; r1.z = o[2].y; r1.w = o[3].y;
    float4 r2; r2.x = o[0].z; r2.y = o[1].z; r2.z = o[2].z; r2.w = o[3].z;
    float4 r3; r3.x = o[0].w; r3.y = o[1].w; r3.z = o[2].w; r3.w = o[3].w;
    *(float4*)(base + ((size_t)(ch    ) * HW + hw) * 4) = r0;
    *(float4*)(base + ((size_t)(ch + 1) * HW + hw) * 4) = r1;
    *(float4*)(base + ((size_t)(ch + 2) * HW + hw) * 4) = r2;
    *(float4*)(base + ((size_t)(ch + 3) * HW + hw) * 4) = r3;
}

// ============================================================================
// K4: conv3x3 (feat4 -> 640ch) implicit GEMM [640,4608]x[4608,HW], tf32 mma.
// 4 warps, 64x64 warp tile, double-buffered smem, one sync per k-tile.
// ============================================================================
__global__ __launch_bounds__(128) void k_mask(const float* __restrict__ w_mask,
                                              const float* __restrict__ b_mask)
{
    extern __shared__ __align__(16) uint8_t smem_raw[];
    uint2* Abuf[2] = { (uint2*)smem_raw, (uint2*)(smem_raw + ASZ) };
    uint2* Bbuf[2] = { (uint2*)(smem_raw + 2 * ASZ), (uint2*)(smem_raw + 2 * ASZ + BSZ) };

    const int c0  = blockIdx.y * 128;
    const int p0  = blockIdx.x * 128;
    const int n   = p0 / HW;
    const int hw0 = p0 - n * HW;
    const float* F = g_cv1 + ((size_t)n * C5 + BC) * HW;   // feat4 (post IN+ReLU)
    const int tid  = threadIdx.x;
    const int lane = tid & 31;
    const int wid  = tid >> 5;
    const int warp_m = wid & 1;
    const int warp_n = wid >> 1;
    const int lr = lane >> 2;
    const int lq = lane & 3;

    const int am  = tid >> 4;
    const int app = tid & 15;
    const int aklo = ((app >> 2) << 3) + (app & 3);
    const int bcol = tid;
    const int phh0 = (hw0 + bcol) / 96;
    const int pww0 = (hw0 + bcol) - phh0 * 96;

    auto gB = [&](int kk) -> float {
        int ci = kk / 9;
        int tap = kk - ci * 9;
        int dy = tap / 3 - 1;
        int dx = tap - (tap / 3) * 3 - 1;
        int hh = phh0 + dy, ww = pww0 + dx;
        float v = 0.f;
        if ((unsigned)hh < 96u && (unsigned)ww < 96u)
            v = F[(size_t)ci * HW + hh * 96 + ww];
        return v;
    };

    float acc[4][8][4];
#pragma unroll
    for (int mt = 0; mt < 4; ++mt)
#pragma unroll
        for (int nt = 0; nt < 8; ++nt)
#pragma unroll
            for (int r = 0; r < 4; ++r) acc[mt][nt][r] = 0.f;

    float2 rA[16], rB[16];
    // prologue: stage tile 0 into buffer 0
#pragma unroll
    for (int j = 0; j < 16; ++j) {
        const float* W = w_mask + (size_t)(c0 + am + 8 * j) * KMASK;
        uint2 v; v.x = to_tf32(W[aklo]); v.y = to_tf32(W[aklo + 4]);
        Abuf[0][(am + 8 * j) * APITCH + app] = v;
    }
#pragma unroll
    for (int pr = 0; pr < 16; ++pr) {
        int klo = ((pr >> 2) << 3) + (pr & 3);
        uint2 v; v.x = to_tf32(gB(klo)); v.y = to_tf32(gB(klo + 4));
        Bbuf[0][pr * BPITCH + bcol] = v;
    }
    __syncthreads();

    const int NT = KMASK / 32;   // 144
    for (int kt = 0; kt < NT; ++kt) {
        const bool more = (kt + 1 < NT);
        if (more) {
            const int k0n = (kt + 1) * 32;
#pragma unroll
            for (int j = 0; j < 16; ++j) {
                const float* W = w_mask + (size_t)(c0 + am + 8 * j) * KMASK + k0n;
                rA[j].x = W[aklo];
                rA[j].y = W[aklo + 4];
            }
#pragma unroll
            for (int pr = 0; pr < 16; ++pr) {
                int klo = k0n + ((pr >> 2) << 3) + (pr & 3);
                rB[pr].x = gB(klo);
                rB[pr].y = gB(klo + 4);
            }
        }
        gemm_tile64(Abuf[kt & 1], Bbuf[kt & 1], acc, warp_m, warp_n, lr, lq);
        if (more) {
            uint2* An = Abuf[(kt + 1) & 1];
            uint2* Bn = Bbuf[(kt + 1) & 1];
#pragma unroll
            for (int j = 0; j < 16; ++j) {
                uint2 v; v.x = to_tf32(rA[j].x); v.y = to_tf32(rA[j].y);
                An[(am + 8 * j) * APITCH + app] = v;
            }
#pragma unroll
            for (int pr = 0; pr < 16; ++pr) {
                uint2 v; v.x = to_tf32(rB[pr].x); v.y = to_tf32(rB[pr].y);
                Bn[pr * BPITCH + bcol] = v;
            }
        }
        __syncthreads();
    }

#pragma unroll
    for (int mt = 0; mt < 4; ++mt) {
        int c_lo = c0 + warp_m * 64 + mt * 16 + lr;
        int c_hi = c_lo + 8;
        float bias_lo = b_mask[c_lo];
        float bias_hi = b_mask[c_hi];
#pragma unroll
        for (int nt = 0; nt < 8; ++nt) {
            int p = hw0 + warp_n * 64 + nt * 8 + 2 * lq;
            float v0 = acc[mt][nt][0] + bias_lo;
            float v1 = acc[mt][nt][1] + bias_lo;
            float v2 = acc[mt][nt][2] + bias_hi;
            float v3 = acc[mt][nt][3] + bias_hi;
            float2 lo, hi;
            lo.x = 1.f / (1.f + __expf(-v0));
            lo.y = 1.f / (1.f + __expf(-v1));
            hi.x = 1.f / (1.f + __expf(-v2));
            hi.y = 1.f / (1.f + __expf(-v3));
            *(float2*)(g_mask + ((size_t)n * C5 + c_lo) * HW + p) = lo;
            *(float2*)(g_mask + ((size_t)n * C5 + c_hi) * HW + p) = hi;
        }
    }
}

// ============================================================================
// K5: final conv1x1 [256,640] on (align*mask), tf32 mma, double-buffered, ReLU.
// ============================================================================
__global__ __launch_bounds__(128) void k_final(const float* __restrict__ w_border,
    const float* __restrict__ b_border, float* __restrict__ out)
{
    extern __shared__ __align__(16) uint8_t smem_raw[];
    uint2* Abuf[2] = { (uint2*)smem_raw, (uint2*)(smem_raw + ASZ) };
    uint2* Bbuf[2] = { (uint2*)(smem_raw + 2 * ASZ), (uint2*)(smem_raw + 2 * ASZ + BSZ) };

    const int c0  = blockIdx.y * 128;
    const int p0  = blockIdx.x * 128;
    const int n   = p0 / HW;
    const int hw0 = p0 - n * HW;
    const int tid  = threadIdx.x;
    const int lane = tid & 31;
    const int wid  = tid >> 5;
    const int warp_m = wid & 1;
    const int warp_n = wid >> 1;
    const int lr = lane >> 2;
    const int lq = lane & 3;

    const int am  = tid >> 4;
    const int app = tid & 15;
    const int aklo = ((app >> 2) << 3) + (app & 3);
    const int bcol = tid;

    const float* ltrb_n = g_ltrb + (size_t)n * C4 * HW + hw0 + bcol;
    const float* fms_n  = g_cv1  + (size_t)n * C5 * HW + hw0 + bcol;  // ch0..127 = fm_short
    const float* mask_n = g_mask + (size_t)n * C5 * HW + hw0 + bcol;

    auto loadB = [&](int kk) -> float {
        float a = (kk < C4) ? ltrb_n[(size_t)kk * HW]
                            : fms_n[(size_t)(kk - C4) * HW];
        return a * mask_n[(size_t)kk * HW];
    };

    float acc[4][8][4];
#pragma unroll
    for (int mt = 0; mt < 4; ++mt)
#pragma unroll
        for (int nt = 0; nt < 8; ++nt)
#pragma unroll
            for (int r = 0; r < 4; ++r) acc[mt][nt][r] = 0.f;

    float2 rA[16], rB[16];
    // prologue: stage tile 0 into buffer 0
#pragma unroll
    for (int j = 0; j < 16; ++j) {
        const float* W = w_border + (size_t)(c0 + am + 8 * j) * C5;
        uint2 v; v.x = to_tf32(W[aklo]); v.y = to_tf32(W[aklo + 4]);
        Abuf[0][(am + 8 * j) * APITCH + app] = v;
    }
#pragma unroll
    for (int pr = 0; pr < 16; ++pr) {
        int klo = ((pr >> 2) << 3) + (pr & 3);
        uint2 v; v.x = to_tf32(loadB(klo)); v.y = to_tf32(loadB(klo + 4));
        Bbuf[0][pr * BPITCH + bcol] = v;
    }
    __syncthreads();

    const int NT = C5 / 32;
    for (int kt = 0; kt < NT; ++kt) {
        const bool more = (kt + 1 < NT);
        if (more) {
            int k0 = (kt + 1) * 32;
#pragma unroll
            for (int j = 0; j < 16; ++j) {
                const float* W = w_border + (size_t)(c0 + am + 8 * j) * C5 + k0;
                rA[j].x = W[aklo];
                rA[j].y = W[aklo + 4];
            }
#pragma unroll
            for (int pr = 0; pr < 16; ++pr) {
                int klo = k0 + ((pr >> 2) << 3) + (pr & 3);
                rB[pr].x = loadB(klo);
                rB[pr].y = loadB(klo + 4);
            }
        }
        gemm_tile64(Abuf[kt & 1], Bbuf[kt & 1], acc, warp_m, warp_n, lr, lq);
        if (more) {
            uint2* An = Abuf[(kt + 1) & 1];
            uint2* Bn = Bbuf[(kt + 1) & 1];
#pragma unroll
            for (int j = 0; j < 16; ++j) {
                uint2 v; v.x = to_tf32(rA[j].x); v.y = to_tf32(rA[j].y);
                An[(am + 8 * j) * APITCH + app] = v;
            }
#pragma unroll
            for (int pr = 0; pr < 16; ++pr) {
                uint2 v; v.x = to_tf32(rB[pr].x); v.y = to_tf32(rB[pr].y);
                Bn[pr * BPITCH + bcol] = v;
            }
        }
        __syncthreads();
    }

#pragma unroll
    for (int mt = 0; mt < 4; ++mt) {
        int c_lo = c0 + warp_m * 64 + mt * 16 + lr;
        int c_hi = c_lo + 8;
        float bias_lo = b_border[c_lo];
        float bias_hi = b_border[c_hi];
#pragma unroll
        for (int nt = 0; nt < 8; ++nt) {
            int p = hw0 + warp_n * 64 + nt * 8 + 2 * lq;
            float2 lo, hi;
            lo.x = fmaxf(acc[mt][nt][0] + bias_lo, 0.f);
            lo.y = fmaxf(acc[mt][nt][1] + bias_lo, 0.f);
            hi.x = fmaxf(acc[mt][nt][2] + bias_hi, 0.f);
            hi.y = fmaxf(acc[mt][nt][3] + bias_hi, 0.f);
            *(float2*)(out + ((size_t)n * COUT + c_lo) * HW + p) = lo;
            *(float2*)(out + ((size_t)n * COUT + c_hi) * HW + p) = hi;
        }
    }
}

// ============================================================================
extern "C" void kernel_launch(void* const* d_in, const int* in_sizes, int n_in,
                              void* d_out, int out_size)
{
    const float* feature  = (const float*)d_in[0];
    const float* boxes    = (const float*)d_in[1];
    // d_in[2] = wh (unused by forward)
    const float* w_cur    = (const float*)d_in[3];
    const float* b_cur    = (const float*)d_in[4];
    const float* w_ltrb   = (const float*)d_in[5];
    const float* b_ltrb   = (const float*)d_in[6];
    const float* w_mask   = (const float*)d_in[7];
    const float* b_mask   = (const float*)d_in[8];
    const float* w_border = (const float*)d_in[9];
    const float* b_border = (const float*)d_in[10];
    float* out = (float*)d_out;

    static bool attr_done = false;
    if (!attr_done) {
        cudaFuncSetAttribute(k_conv1, cudaFuncAttributeMaxDynamicSharedMemorySize, SMEM_GEMM);
        cudaFuncSetAttribute(k_mask,  cudaFuncAttributeMaxDynamicSharedMemorySize, SMEM_GEMM);
        cudaFuncSetAttribute(k_final, cudaFuncAttributeMaxDynamicSharedMemorySize, SMEM_GEMM);
        attr_done = true;
    }

    k_conv1<<<dim3(144, 5), 128, SMEM_GEMM>>>(feature, w_cur, b_cur, w_ltrb, b_ltrb);
    k_inorm<<<NB * C5, 256>>>();
    k_transpose<<<dim3(288, 16, NB), dim3(32, 8)>>>();
    k_border<<<NB * HW / 4, 128>>>(boxes);
    k_mask<<<dim3(144, 5), 128, SMEM_GEMM>>>(w_mask, b_mask);
    k_final<<<dim3(144, 2), 128, SMEM_GEMM>>>(w_border, b_border, out);
}

// round 14
// speedup vs baseline: 1.3011x; 1.3011x over previous
#include <cuda_runtime.h>
#include <math.h>
#include <stdint.h>

#define NB   2
#define CIN  256
#define Hh   96
#define Ww   96
#define HW   9216
#define BC   128
#define C4   512
#define C5   640
#define COUT 256
#define KMASK 4608   // 512*9

#define APITCH 20    // uint2 per A row (16 used + 4 pad); 20 % 16 == 4 -> conflict-free
#define BPITCH 132   // uint2 per B k-row; 132 % 16 == 4 -> conflict-free

// ---- scratch (static device arrays; no allocation) ----
__device__ float g_cv1[(size_t)NB*C5*HW];      // conv1x1 out: ch 0..127 = cur, 128..639 = ltrb (post-IN in place)
__device__ float g_f4t[(size_t)NB*4*HW*BC];    // feat4 transposed: [n][border][hw][c]
__device__ float g_ltrb[(size_t)NB*C4*HW];     // border-align output in the reshaped [n][512][HW] layout
__device__ float g_mask[(size_t)NB*C5*HW];     // sigmoid(conv3x3)

__device__ __forceinline__ uint32_t to_tf32(float x) {
    uint32_t y;
    asm("cvt.rna.tf32.f32 %0, %1;" : "=r"(y) : "f"(x));
    return y;
}

__device__ __forceinline__ void mma_tf32(float* c, const uint32_t* a, const uint32_t* b) {
    asm volatile(
        "mma.sync.aligned.m16n8k8.row.col.f32.tf32.tf32.f32 "
        "{%0,%1,%2,%3}, {%4,%5,%6,%7}, {%8,%9}, {%0,%1,%2,%3};"
        : "+f"(c[0]), "+f"(c[1]), "+f"(c[2]), "+f"(c[3])
        : "r"(a[0]), "r"(a[1]), "r"(a[2]), "r"(a[3]), "r"(b[0]), "r"(b[1]));
}

// 4-warp tile compute: warp tile 64(M) x 64(N), block tile 128x128x32.
// 16 LDS.64 per 32 MMAs per k-step (0.5 loads/MMA).
__device__ __forceinline__ void gemm_tile64(const uint2* As2, const uint2* Bs2,
    float acc[4][8][4], int warp_m, int warp_n, int lr, int lq)
{
#pragma unroll
    for (int ks = 0; ks < 4; ++ks) {
        const int kp = ks * 4 + lq;
        uint32_t afr[4][4], bfr[8][2];
#pragma unroll
        for (int mt = 0; mt < 4; ++mt) {
            int row = warp_m * 64 + mt * 16 + lr;
            uint2 alo = As2[row * APITCH + kp];
            uint2 ahi = As2[(row + 8) * APITCH + kp];
            afr[mt][0] = alo.x; afr[mt][1] = ahi.x;
            afr[mt][2] = alo.y; afr[mt][3] = ahi.y;
        }
#pragma unroll
        for (int nt = 0; nt < 8; ++nt) {
            int col = warp_n * 64 + nt * 8 + lr;
            uint2 b = Bs2[kp * BPITCH + col];
            bfr[nt][0] = b.x; bfr[nt][1] = b.y;
        }
#pragma unroll
        for (int mt = 0; mt < 4; ++mt)
#pragma unroll
            for (int nt = 0; nt < 8; ++nt)
                mma_tf32(acc[mt][nt], afr[mt], bfr[nt]);
    }
}

// ============================================================================
// K1: fused conv1x1 (cur||ltrb) = GEMM [640,256]x[256,HW] + bias, tf32 mma.
// 4 warps, warp tile 64x64.
// ============================================================================
__global__ __launch_bounds__(128) void k_conv1(const float* __restrict__ feat,
    const float* __restrict__ w_cur, const float* __restrict__ b_cur,
    const float* __restrict__ w_ltrb, const float* __restrict__ b_ltrb)
{
    __shared__ uint2 As2[128 * APITCH];
    __shared__ uint2 Bs2[16 * BPITCH];
    const int c0  = blockIdx.y * 128;
    const int p0  = blockIdx.x * 128;
    const int n   = p0 / HW;
    const int hw0 = p0 - n * HW;
    const float* X = feat + (size_t)n * CIN * HW + hw0;
    const int tid  = threadIdx.x;          // 0..127
    const int lane = tid & 31;
    const int wid  = tid >> 5;
    const int warp_m = wid & 1;
    const int warp_n = wid >> 1;
    const int lr = lane >> 2;
    const int lq = lane & 3;

    const int am  = tid >> 4;              // 0..7
    const int app = tid & 15;
    const int aklo = ((app >> 2) << 3) + (app & 3);
    const int bcol = tid;                  // 0..127

    float acc[4][8][4];
#pragma unroll
    for (int mt = 0; mt < 4; ++mt)
#pragma unroll
        for (int nt = 0; nt < 8; ++nt)
#pragma unroll
            for (int r = 0; r < 4; ++r) acc[mt][nt][r] = 0.f;

    float2 rA[16], rB[16];
#pragma unroll
    for (int j = 0; j < 16; ++j) {
        int c = c0 + am + 8 * j;
        const float* W = (c < BC) ? (w_cur + c * CIN) : (w_ltrb + (c - BC) * CIN);
        rA[j].x = W[aklo];
        rA[j].y = W[aklo + 4];
    }
#pragma unroll
    for (int pr = 0; pr < 16; ++pr) {
        int klo = ((pr >> 2) << 3) + (pr & 3);
        rB[pr].x = X[(size_t)klo * HW + bcol];
        rB[pr].y = X[(size_t)(klo + 4) * HW + bcol];
    }

    const int NT = CIN / 32;
    for (int kt = 0; kt < NT; ++kt) {
#pragma unroll
        for (int j = 0; j < 16; ++j) {
            uint2 v; v.x = to_tf32(rA[j].x); v.y = to_tf32(rA[j].y);
            As2[(am + 8 * j) * APITCH + app] = v;
        }
#pragma unroll
        for (int pr = 0; pr < 16; ++pr) {
            uint2 v; v.x = to_tf32(rB[pr].x); v.y = to_tf32(rB[pr].y);
            Bs2[pr * BPITCH + bcol] = v;
        }
        __syncthreads();
        if (kt + 1 < NT) {
            int k0 = (kt + 1) * 32;
#pragma unroll
            for (int j = 0; j < 16; ++j) {
                int c = c0 + am + 8 * j;
                const float* W = (c < BC) ? (w_cur + c * CIN) : (w_ltrb + (c - BC) * CIN);
                rA[j].x = W[k0 + aklo];
                rA[j].y = W[k0 + aklo + 4];
            }
#pragma unroll
            for (int pr = 0; pr < 16; ++pr) {
                int klo = k0 + ((pr >> 2) << 3) + (pr & 3);
                rB[pr].x = X[(size_t)klo * HW + bcol];
                rB[pr].y = X[(size_t)(klo + 4) * HW + bcol];
            }
        }
        gemm_tile64(As2, Bs2, acc, warp_m, warp_n, lr, lq);
        __syncthreads();
    }

#pragma unroll
    for (int mt = 0; mt < 4; ++mt) {
        int c_lo = c0 + warp_m * 64 + mt * 16 + lr;
        int c_hi = c_lo + 8;
        float bias_lo = (c_lo < BC) ? b_cur[c_lo] : b_ltrb[c_lo - BC];
        float bias_hi = (c_hi < BC) ? b_cur[c_hi] : b_ltrb[c_hi - BC];
#pragma unroll
        for (int nt = 0; nt < 8; ++nt) {
            int p = hw0 + warp_n * 64 + nt * 8 + 2 * lq;
            float2 lo, hi;
            lo.x = acc[mt][nt][0] + bias_lo;
            lo.y = acc[mt][nt][1] + bias_lo;
            hi.x = acc[mt][nt][2] + bias_hi;
            hi.y = acc[mt][nt][3] + bias_hi;
            *(float2*)(g_cv1 + ((size_t)n * C5 + c_lo) * HW + p) = lo;
            *(float2*)(g_cv1 + ((size_t)n * C5 + c_hi) * HW + p) = hi;
        }
    }
}

// ============================================================================
// K2: instance norm (biased var, eps=1e-5) + ReLU, in place. One block per (n,c).
// ============================================================================
__global__ __launch_bounds__(256) void k_inorm()
{
    const int nc = blockIdx.x;          // n*C5 + c
    float4* base = (float4*)(g_cv1 + (size_t)nc * HW);
    const int tid = threadIdx.x;
    float s = 0.f, q = 0.f;
#pragma unroll
    for (int i = tid; i < HW / 4; i += 256) {
        float4 v = base[i];
        s += v.x + v.y + v.z + v.w;
        q += v.x * v.x + v.y * v.y + v.z * v.z + v.w * v.w;
    }
    __shared__ float ss[256], qq[256];
    ss[tid] = s; qq[tid] = q;
    __syncthreads();
    for (int off = 128; off > 0; off >>= 1) {
        if (tid < off) { ss[tid] += ss[tid + off]; qq[tid] += qq[tid + off]; }
        __syncthreads();
    }
    const float mean = ss[0] * (1.f / HW);
    const float var  = qq[0] * (1.f / HW) - mean * mean;
    const float rstd = rsqrtf(var + 1e-5f);
#pragma unroll
    for (int i = tid; i < HW / 4; i += 256) {
        float4 v = base[i];
        v.x = fmaxf((v.x - mean) * rstd, 0.f);
        v.y = fmaxf((v.y - mean) * rstd, 0.f);
        v.z = fmaxf((v.z - mean) * rstd, 0.f);
        v.w = fmaxf((v.w - mean) * rstd, 0.f);
        base[i] = v;
    }
}

// ============================================================================
// K2b: transpose feat4 (channels 128..639 of g_cv1) into [n][b][hw][c]
// ============================================================================
__global__ void k_transpose()
{
    __shared__ float t[32][33];
    const int n   = blockIdx.z;
    const int c0  = blockIdx.y * 32;    // 0..511 relative to feat4
    const int hw0 = blockIdx.x * 32;
    const int tx = threadIdx.x, ty = threadIdx.y;   // 32 x 8
    const float* src = g_cv1 + ((size_t)n * C5 + BC + c0) * HW + hw0;
#pragma unroll
    for (int r = 0; r < 4; ++r)
        t[ty + r * 8][tx] = src[(size_t)(ty + r * 8) * HW + tx];
    __syncthreads();
    const int b   = c0 >> 7;
    const int cc0 = c0 & 127;
    float* dst = g_f4t + (((size_t)n * 4 + b) * HW + hw0) * BC + cc0;
#pragma unroll
    for (int r = 0; r < 4; ++r)
        dst[(size_t)(ty + r * 8) * BC + tx] = t[tx][ty + r * 8];
}

// ============================================================================
// K3: BorderAlign. 4 pixels per block; params precomputed to smem; each thread
// handles 4 channels (float4 gathers) for one pixel.
// ============================================================================
struct SampP { int o00, o01, o10, o11; float w00, w01, w10, w11; };

__global__ __launch_bounds__(128) void k_border(const float* __restrict__ boxes)
{
    __shared__ SampP sp[4][44];
    const int blk = blockIdx.x;         // pixel quad
    const int t  = threadIdx.x;

    for (int s = t; s < 176; s += 128) {
        const int pix = s / 44, q = s - pix * 44;
        const int b = q / 11, i = q - b * 11;
        const int P = blk * 4 + pix;
        const int n = P / HW, hw = P - n * HW;
        const float4 bx = *(const float4*)(boxes + ((size_t)n * HW + hw) * 4);
        const float bw = (bx.z - bx.x) * 0.1f, bh = (bx.w - bx.y) * 0.1f;
        const float sx = (b == 3) ? bx.z : bx.x;
        const float sy = (b == 2) ? bx.w : bx.y;
        const float dx = (b == 0 || b == 2) ? bw : 0.f;
        const float dy = (b == 1 || b == 3) ? bh : 0.f;
        const float x = sx + dx * (float)i;
        const float y = sy + dy * (float)i;
        const bool valid = (x >= -1.f) && (x <= 96.f) && (y >= -1.f) && (y <= 96.f);
        const float xc = fminf(fmaxf(x, 0.f), 95.f);
        const float yc = fminf(fmaxf(y, 0.f), 95.f);
        int x0 = (int)floorf(xc); if (x0 > 95) x0 = 95;
        int y0 = (int)floorf(yc); if (y0 > 95) y0 = 95;
        const int x1i = x0 + 1 > 95 ? 95 : x0 + 1;
        const int y1i = y0 + 1 > 95 ? 95 : y0 + 1;
        const float lx = (x0 >= 95) ? 0.f : (xc - (float)x0);
        const float ly = (y0 >= 95) ? 0.f : (yc - (float)y0);
        const float hx = 1.f - lx, hy = 1.f - ly;
        const float sv = valid ? 1.f : 0.f;
        SampP p;
        p.o00 = (y0  * 96 + x0 ) * BC;
        p.o01 = (y0  * 96 + x1i) * BC;
        p.o10 = (y1i * 96 + x0 ) * BC;
        p.o11 = (y1i * 96 + x1i) * BC;
        p.w00 = hy * hx * sv;
        p.w01 = hy * lx * sv;
        p.w10 = ly * hx * sv;
        p.w11 = ly * lx * sv;
        sp[pix][q] = p;
    }
    __syncthreads();

    const int half = t >> 5;            // pixel 0..3
    const int ch   = (t & 31) * 4;      // channel quad
    const int P = blk * 4 + half;
    const int n = P / HW, hw = P - n * HW;
    const float* ftn = g_f4t + (size_t)n * 4 * HW * BC + ch;
    float4 o[4];
#pragma unroll
    for (int b = 0; b < 4; ++b) {
        const float* fb = ftn + b * (HW * BC);
        float m0 = -3.4e38f, m1 = -3.4e38f, m2 = -3.4e38f, m3 = -3.4e38f;
#pragma unroll
        for (int i = 0; i < 11; ++i) {
            const SampP p = sp[half][b * 11 + i];
            const float4 v00 = *(const float4*)(fb + p.o00);
            const float4 v01 = *(const float4*)(fb + p.o01);
            const float4 v10 = *(const float4*)(fb + p.o10);
            const float4 v11 = *(const float4*)(fb + p.o11);
            float a0 = p.w00 * v00.x;
            a0 = fmaf(p.w01, v01.x, a0);
            a0 = fmaf(p.w10, v10.x, a0);
            a0 = fmaf(p.w11, v11.x, a0);
            float a1 = p.w00 * v00.y;
            a1 = fmaf(p.w01, v01.y, a1);
            a1 = fmaf(p.w10, v10.y, a1);
            a1 = fmaf(p.w11, v11.y, a1);
            float a2 = p.w00 * v00.z;
            a2 = fmaf(p.w01, v01.z, a2);
            a2 = fmaf(p.w10, v10.z, a2);
            a2 = fmaf(p.w11, v11.z, a2);
            float a3 = p.w00 * v00.w;
            a3 = fmaf(p.w01, v01.w, a3);
            a3 = fmaf(p.w10, v10.w, a3);
            a3 = fmaf(p.w11, v11.w, a3);
            m0 = fmaxf(m0, a0);
            m1 = fmaxf(m1, a1);
            m2 = fmaxf(m2, a2);
            m3 = fmaxf(m3, a3);
        }
        o[b].x = m0; o[b].y = m1; o[b].z = m2; o[b].w = m3;
    }
    float* base = g_ltrb + (size_t)n * C4 * HW;
    float4 r0; r0.x = o[0].x; r0.y = o[1].x; r0.z = o[2].x; r0.w = o[3].x;
    float4 r1; r1.x = o[0].y; r1.y = o[1].y; r1.z = o[2].y; r1.w = o[3].y;
    float4 r2; r2.x = o[0].z; r2.y = o[1].z; r2.z = o[2].z; r2.w = o[3].z;
    float4 r3; r3.x = o[0].w; r3.y = o[1].w; r3.z = o[2].w; r3.w = o[3].w;
    *(float4*)(base + ((size_t)(ch    ) * HW + hw) * 4) = r0;
    *(float4*)(base + ((size_t)(ch + 1) * HW + hw) * 4) = r1;
    *(float4*)(base + ((size_t)(ch + 2) * HW + hw) * 4) = r2;
    *(float4*)(base + ((size_t)(ch + 3) * HW + hw) * 4) = r3;
}

// ============================================================================
// K4: conv3x3 (feat4 -> 640ch) implicit GEMM [640,4608]x[4608,HW], tf32 mma.
// 4 warps, warp tile 64x64.
// ============================================================================
__global__ __launch_bounds__(128) void k_mask(const float* __restrict__ w_mask,
                                              const float* __restrict__ b_mask)
{
    __shared__ uint2 As2[128 * APITCH];
    __shared__ uint2 Bs2[16 * BPITCH];
    const int c0  = blockIdx.y * 128;
    const int p0  = blockIdx.x * 128;
    const int n   = p0 / HW;
    const int hw0 = p0 - n * HW;
    const float* F = g_cv1 + ((size_t)n * C5 + BC) * HW;   // feat4 (post IN+ReLU)
    const int tid  = threadIdx.x;          // 0..127
    const int lane = tid & 31;
    const int wid  = tid >> 5;             // 0..3
    const int warp_m = wid & 1;
    const int warp_n = wid >> 1;
    const int lr = lane >> 2;
    const int lq = lane & 3;

    const int am  = tid >> 4;              // 0..7
    const int app = tid & 15;
    const int aklo = ((app >> 2) << 3) + (app & 3);
    const int bcol = tid;                  // 0..127
    const int phh0 = (hw0 + bcol) / 96;
    const int pww0 = (hw0 + bcol) - phh0 * 96;

    auto gB = [&](int kk) -> float {
        int ci = kk / 9;
        int tap = kk - ci * 9;
        int dy = tap / 3 - 1;
        int dx = tap - (tap / 3) * 3 - 1;
        int hh = phh0 + dy, ww = pww0 + dx;
        float v = 0.f;
        if ((unsigned)hh < 96u && (unsigned)ww < 96u)
            v = F[(size_t)ci * HW + hh * 96 + ww];
        return v;
    };

    float acc[4][8][4];
#pragma unroll
    for (int mt = 0; mt < 4; ++mt)
#pragma unroll
        for (int nt = 0; nt < 8; ++nt)
#pragma unroll
            for (int r = 0; r < 4; ++r) acc[mt][nt][r] = 0.f;

    float2 rA[16], rB[16];
#pragma unroll
    for (int j = 0; j < 16; ++j) {
        const float* W = w_mask + (size_t)(c0 + am + 8 * j) * KMASK;
        rA[j].x = W[aklo];
        rA[j].y = W[aklo + 4];
    }
#pragma unroll
    for (int pr = 0; pr < 16; ++pr) {
        int klo = ((pr >> 2) << 3) + (pr & 3);
        rB[pr].x = gB(klo);
        rB[pr].y = gB(klo + 4);
    }

    const int NT = KMASK / 32;   // 144
    for (int kt = 0; kt < NT; ++kt) {
#pragma unroll
        for (int j = 0; j < 16; ++j) {
            uint2 v; v.x = to_tf32(rA[j].x); v.y = to_tf32(rA[j].y);
            As2[(am + 8 * j) * APITCH + app] = v;
        }
#pragma unroll
        for (int pr = 0; pr < 16; ++pr) {
            uint2 v; v.x = to_tf32(rB[pr].x); v.y = to_tf32(rB[pr].y);
            Bs2[pr * BPITCH + bcol] = v;
        }
        __syncthreads();
        if (kt + 1 < NT) {
            const int k0n = (kt + 1) * 32;
#pragma unroll
            for (int j = 0; j < 16; ++j) {
                const float* W = w_mask + (size_t)(c0 + am + 8 * j) * KMASK + k0n;
                rA[j].x = W[aklo];
                rA[j].y = W[aklo + 4];
            }
#pragma unroll
            for (int pr = 0; pr < 16; ++pr) {
                int klo = k0n + ((pr >> 2) << 3) + (pr & 3);
                rB[pr].x = gB(klo);
                rB[pr].y = gB(klo + 4);
            }
        }
        gemm_tile64(As2, Bs2, acc, warp_m, warp_n, lr, lq);
        __syncthreads();
    }

#pragma unroll
    for (int mt = 0; mt < 4; ++mt) {
        int c_lo = c0 + warp_m * 64 + mt * 16 + lr;
        int c_hi = c_lo + 8;
        float bias_lo = b_mask[c_lo];
        float bias_hi = b_mask[c_hi];
#pragma unroll
        for (int nt = 0; nt < 8; ++nt) {
            int p = hw0 + warp_n * 64 + nt * 8 + 2 * lq;
            float v0 = acc[mt][nt][0] + bias_lo;
            float v1 = acc[mt][nt][1] + bias_lo;
            float v2 = acc[mt][nt][2] + bias_hi;
            float v3 = acc[mt][nt][3] + bias_hi;
            float2 lo, hi;
            lo.x = 1.f / (1.f + __expf(-v0));
            lo.y = 1.f / (1.f + __expf(-v1));
            hi.x = 1.f / (1.f + __expf(-v2));
            hi.y = 1.f / (1.f + __expf(-v3));
            *(float2*)(g_mask + ((size_t)n * C5 + c_lo) * HW + p) = lo;
            *(float2*)(g_mask + ((size_t)n * C5 + c_hi) * HW + p) = hi;
        }
    }
}

// ============================================================================
// K5: final conv1x1 [256,640] on (align*mask), tf32 mma, 4 warps 64x64, ReLU.
// ============================================================================
__global__ __launch_bounds__(128) void k_final(const float* __restrict__ w_border,
    const float* __restrict__ b_border, float* __restrict__ out)
{
    __shared__ uint2 As2[128 * APITCH];
    __shared__ uint2 Bs2[16 * BPITCH];
    const int c0  = blockIdx.y * 128;
    const int p0  = blockIdx.x * 128;
    const int n   = p0 / HW;
    const int hw0 = p0 - n * HW;
    const int tid  = threadIdx.x;          // 0..127
    const int lane = tid & 31;
    const int wid  = tid >> 5;
    const int warp_m = wid & 1;
    const int warp_n = wid >> 1;
    const int lr = lane >> 2;
    const int lq = lane & 3;

    const int am  = tid >> 4;
    const int app = tid & 15;
    const int aklo = ((app >> 2) << 3) + (app & 3);
    const int bcol = tid;

    const float* ltrb_n = g_ltrb + (size_t)n * C4 * HW + hw0 + bcol;
    const float* fms_n  = g_cv1  + (size_t)n * C5 * HW + hw0 + bcol;  // ch0..127 = fm_short
    const float* mask_n = g_mask + (size_t)n * C5 * HW + hw0 + bcol;

    auto loadB = [&](int kk) -> float {
        float a = (kk < C4) ? ltrb_n[(size_t)kk * HW]
                            : fms_n[(size_t)(kk - C4) * HW];
        return a * mask_n[(size_t)kk * HW];
    };

    float acc[4][8][4];
#pragma unroll
    for (int mt = 0; mt < 4; ++mt)
#pragma unroll
        for (int nt = 0; nt < 8; ++nt)
#pragma unroll
            for (int r = 0; r < 4; ++r) acc[mt][nt][r] = 0.f;

    float2 rA[16], rB[16];
#pragma unroll
    for (int j = 0; j < 16; ++j) {
        const float* W = w_border + (size_t)(c0 + am + 8 * j) * C5;
        rA[j].x = W[aklo];
        rA[j].y = W[aklo + 4];
    }
#pragma unroll
    for (int pr = 0; pr < 16; ++pr) {
        int klo = ((pr >> 2) << 3) + (pr & 3);
        rB[pr].x = loadB(klo);
        rB[pr].y = loadB(klo + 4);
    }

    const int NT = C5 / 32;
    for (int kt = 0; kt < NT; ++kt) {
#pragma unroll
        for (int j = 0; j < 16; ++j) {
            uint2 v; v.x = to_tf32(rA[j].x); v.y = to_tf32(rA[j].y);
            As2[(am + 8 * j) * APITCH + app] = v;
        }
#pragma unroll
        for (int pr = 0; pr < 16; ++pr) {
            uint2 v; v.x = to_tf32(rB[pr].x); v.y = to_tf32(rB[pr].y);
            Bs2[pr * BPITCH + bcol] = v;
        }
        __syncthreads();
        if (kt + 1 < NT) {
            int k0 = (kt + 1) * 32;
#pragma unroll
            for (int j = 0; j < 16; ++j) {
                const float* W = w_border + (size_t)(c0 + am + 8 * j) * C5 + k0;
                rA[j].x = W[aklo];
                rA[j].y = W[aklo + 4];
            }
#pragma unroll
            for (int pr = 0; pr < 16; ++pr) {
                int klo = k0 + ((pr >> 2) << 3) + (pr & 3);
                rB[pr].x = loadB(klo);
                rB[pr].y = loadB(klo + 4);
            }
        }
        gemm_tile64(As2, Bs2, acc, warp_m, warp_n, lr, lq);
        __syncthreads();
    }

#pragma unroll
    for (int mt = 0; mt < 4; ++mt) {
        int c_lo = c0 + warp_m * 64 + mt * 16 + lr;
        int c_hi = c_lo + 8;
        float bias_lo = b_border[c_lo];
        float bias_hi = b_border[c_hi];
#pragma unroll
        for (int nt = 0; nt < 8; ++nt) {
            int p = hw0 + warp_n * 64 + nt * 8 + 2 * lq;
            float2 lo, hi;
            lo.x = fmaxf(acc[mt][nt][0] + bias_lo, 0.f);
            lo.y = fmaxf(acc[mt][nt][1] + bias_lo, 0.f);
            hi.x = fmaxf(acc[mt][nt][2] + bias_hi, 0.f);
            hi.y = fmaxf(acc[mt][nt][3] + bias_hi, 0.f);
            *(float2*)(out + ((size_t)n * COUT + c_lo) * HW + p) = lo;
            *(float2*)(out + ((size_t)n * COUT + c_hi) * HW + p) = hi;
        }
    }
}

// ============================================================================
extern "C" void kernel_launch(void* const* d_in, const int* in_sizes, int n_in,
                              void* d_out, int out_size)
{
    const float* feature  = (const float*)d_in[0];
    const float* boxes    = (const float*)d_in[1];
    // d_in[2] = wh (unused by forward)
    const float* w_cur    = (const float*)d_in[3];
    const float* b_cur    = (const float*)d_in[4];
    const float* w_ltrb   = (const float*)d_in[5];
    const float* b_ltrb   = (const float*)d_in[6];
    const float* w_mask   = (const float*)d_in[7];
    const float* b_mask   = (const float*)d_in[8];
    const float* w_border = (const float*)d_in[9];
    const float* b_border = (const float*)d_in[10];
    float* out = (float*)d_out;

    k_conv1<<<dim3(144, 5), 128>>>(feature, w_cur, b_cur, w_ltrb, b_ltrb);
    k_inorm<<<NB * C5, 256>>>();
    k_transpose<<<dim3(288, 16, NB), dim3(32, 8)>>>();
    k_border<<<NB * HW / 4, 128>>>(boxes);
    k_mask<<<dim3(144, 5), 128>>>(w_mask, b_mask);
    k_final<<<dim3(144, 2), 128>>>(w_border, b_border, out);
}

// round 15
// speedup vs baseline: 1.3372x; 1.0277x over previous
#include <cuda_runtime.h>
#include <math.h>
#include <stdint.h>

#define NB   2
#define CIN  256
#define Hh   96
#define Ww   96
#define HW   9216
#define BC   128
#define C4   512
#define C5   640
#define COUT 256
#define KMASK 4608   // 512*9

#define APITCH 20    // uint2 per A row (16 used + 4 pad); 20 % 16 == 4 -> conflict-free
#define BPITCH 132   // uint2 per B k-row; 132 % 16 == 4 -> conflict-free

// ---- scratch (static device arrays; no allocation) ----
__device__ float g_cv1[(size_t)NB*C5*HW];      // conv1x1 out: ch 0..127 = cur, 128..639 = ltrb (post-IN in place)
__device__ float g_f4t[(size_t)NB*4*HW*BC];    // feat4 transposed: [n][border][hw][c]
__device__ float g_ltrb[(size_t)NB*C4*HW];     // border-align output in the reshaped [n][512][HW] layout
__device__ float g_mask[(size_t)NB*C5*HW];     // sigmoid(conv3x3)

__device__ __forceinline__ uint32_t to_tf32(float x) {
    uint32_t y;
    asm("cvt.rna.tf32.f32 %0, %1;" : "=r"(y) : "f"(x));
    return y;
}

__device__ __forceinline__ void mma_tf32(float* c, const uint32_t* a, const uint32_t* b) {
    asm volatile(
        "mma.sync.aligned.m16n8k8.row.col.f32.tf32.tf32.f32 "
        "{%0,%1,%2,%3}, {%4,%5,%6,%7}, {%8,%9}, {%0,%1,%2,%3};"
        : "+f"(c[0]), "+f"(c[1]), "+f"(c[2]), "+f"(c[3])
        : "r"(a[0]), "r"(a[1]), "r"(a[2]), "r"(a[3]), "r"(b[0]), "r"(b[1]));
}

// 4-warp tile compute: warp tile 64(M) x 64(N), block tile 128x128x32.
// 16 LDS.64 per 32 MMAs per k-step (0.5 loads/MMA).
__device__ __forceinline__ void gemm_tile64(const uint2* As2, const uint2* Bs2,
    float acc[4][8][4], int warp_m, int warp_n, int lr, int lq)
{
#pragma unroll
    for (int ks = 0; ks < 4; ++ks) {
        const int kp = ks * 4 + lq;
        uint32_t afr[4][4], bfr[8][2];
#pragma unroll
        for (int mt = 0; mt < 4; ++mt) {
            int row = warp_m * 64 + mt * 16 + lr;
            uint2 alo = As2[row * APITCH + kp];
            uint2 ahi = As2[(row + 8) * APITCH + kp];
            afr[mt][0] = alo.x; afr[mt][1] = ahi.x;
            afr[mt][2] = alo.y; afr[mt][3] = ahi.y;
        }
#pragma unroll
        for (int nt = 0; nt < 8; ++nt) {
            int col = warp_n * 64 + nt * 8 + lr;
            uint2 b = Bs2[kp * BPITCH + col];
            bfr[nt][0] = b.x; bfr[nt][1] = b.y;
        }
#pragma unroll
        for (int mt = 0; mt < 4; ++mt)
#pragma unroll
            for (int nt = 0; nt < 8; ++nt)
                mma_tf32(acc[mt][nt], afr[mt], bfr[nt]);
    }
}

// ============================================================================
// K1: fused conv1x1 (cur||ltrb) = GEMM [640,256]x[256,HW] + bias, tf32 mma.
// 4 warps, warp tile 64x64.
// ============================================================================
__global__ __launch_bounds__(128) void k_conv1(const float* __restrict__ feat,
    const float* __restrict__ w_cur, const float* __restrict__ b_cur,
    const float* __restrict__ w_ltrb, const float* __restrict__ b_ltrb)
{
    __shared__ uint2 As2[128 * APITCH];
    __shared__ uint2 Bs2[16 * BPITCH];
    const int c0  = blockIdx.y * 128;
    const int p0  = blockIdx.x * 128;
    const int n   = p0 / HW;
    const int hw0 = p0 - n * HW;
    const float* X = feat + (size_t)n * CIN * HW + hw0;
    const int tid  = threadIdx.x;          // 0..127
    const int lane = tid & 31;
    const int wid  = tid >> 5;
    const int warp_m = wid & 1;
    const int warp_n = wid >> 1;
    const int lr = lane >> 2;
    const int lq = lane & 3;

    const int am  = tid >> 4;              // 0..7
    const int app = tid & 15;
    const int aklo = ((app >> 2) << 3) + (app & 3);
    const int bcol = tid;                  // 0..127

    float acc[4][8][4];
#pragma unroll
    for (int mt = 0; mt < 4; ++mt)
#pragma unroll
        for (int nt = 0; nt < 8; ++nt)
#pragma unroll
            for (int r = 0; r < 4; ++r) acc[mt][nt][r] = 0.f;

    float2 rA[16], rB[16];
#pragma unroll
    for (int j = 0; j < 16; ++j) {
        int c = c0 + am + 8 * j;
        const float* W = (c < BC) ? (w_cur + c * CIN) : (w_ltrb + (c - BC) * CIN);
        rA[j].x = W[aklo];
        rA[j].y = W[aklo + 4];
    }
#pragma unroll
    for (int pr = 0; pr < 16; ++pr) {
        int klo = ((pr >> 2) << 3) + (pr & 3);
        rB[pr].x = X[(size_t)klo * HW + bcol];
        rB[pr].y = X[(size_t)(klo + 4) * HW + bcol];
    }

    const int NT = CIN / 32;
    for (int kt = 0; kt < NT; ++kt) {
#pragma unroll
        for (int j = 0; j < 16; ++j) {
            uint2 v; v.x = to_tf32(rA[j].x); v.y = to_tf32(rA[j].y);
            As2[(am + 8 * j) * APITCH + app] = v;
        }
#pragma unroll
        for (int pr = 0; pr < 16; ++pr) {
            uint2 v; v.x = to_tf32(rB[pr].x); v.y = to_tf32(rB[pr].y);
            Bs2[pr * BPITCH + bcol] = v;
        }
        __syncthreads();
        if (kt + 1 < NT) {
            int k0 = (kt + 1) * 32;
#pragma unroll
            for (int j = 0; j < 16; ++j) {
                int c = c0 + am + 8 * j;
                const float* W = (c < BC) ? (w_cur + c * CIN) : (w_ltrb + (c - BC) * CIN);
                rA[j].x = W[k0 + aklo];
                rA[j].y = W[k0 + aklo + 4];
            }
#pragma unroll
            for (int pr = 0; pr < 16; ++pr) {
                int klo = k0 + ((pr >> 2) << 3) + (pr & 3);
                rB[pr].x = X[(size_t)klo * HW + bcol];
                rB[pr].y = X[(size_t)(klo + 4) * HW + bcol];
            }
        }
        gemm_tile64(As2, Bs2, acc, warp_m, warp_n, lr, lq);
        __syncthreads();
    }

#pragma unroll
    for (int mt = 0; mt < 4; ++mt) {
        int c_lo = c0 + warp_m * 64 + mt * 16 + lr;
        int c_hi = c_lo + 8;
        float bias_lo = (c_lo < BC) ? b_cur[c_lo] : b_ltrb[c_lo - BC];
        float bias_hi = (c_hi < BC) ? b_cur[c_hi] : b_ltrb[c_hi - BC];
#pragma unroll
        for (int nt = 0; nt < 8; ++nt) {
            int p = hw0 + warp_n * 64 + nt * 8 + 2 * lq;
            float2 lo, hi;
            lo.x = acc[mt][nt][0] + bias_lo;
            lo.y = acc[mt][nt][1] + bias_lo;
            hi.x = acc[mt][nt][2] + bias_hi;
            hi.y = acc[mt][nt][3] + bias_hi;
            *(float2*)(g_cv1 + ((size_t)n * C5 + c_lo) * HW + p) = lo;
            *(float2*)(g_cv1 + ((size_t)n * C5 + c_hi) * HW + p) = hi;
        }
    }
}

// ============================================================================
// K2: instance norm (biased var, eps=1e-5) + ReLU, in place. One block per (n,c).
// ============================================================================
__global__ __launch_bounds__(256) void k_inorm()
{
    const int nc = blockIdx.x;          // n*C5 + c
    float4* base = (float4*)(g_cv1 + (size_t)nc * HW);
    const int tid = threadIdx.x;
    float s = 0.f, q = 0.f;
#pragma unroll
    for (int i = tid; i < HW / 4; i += 256) {
        float4 v = base[i];
        s += v.x + v.y + v.z + v.w;
        q += v.x * v.x + v.y * v.y + v.z * v.z + v.w * v.w;
    }
    __shared__ float ss[256], qq[256];
    ss[tid] = s; qq[tid] = q;
    __syncthreads();
    for (int off = 128; off > 0; off >>= 1) {
        if (tid < off) { ss[tid] += ss[tid + off]; qq[tid] += qq[tid + off]; }
        __syncthreads();
    }
    const float mean = ss[0] * (1.f / HW);
    const float var  = qq[0] * (1.f / HW) - mean * mean;
    const float rstd = rsqrtf(var + 1e-5f);
#pragma unroll
    for (int i = tid; i < HW / 4; i += 256) {
        float4 v = base[i];
        v.x = fmaxf((v.x - mean) * rstd, 0.f);
        v.y = fmaxf((v.y - mean) * rstd, 0.f);
        v.z = fmaxf((v.z - mean) * rstd, 0.f);
        v.w = fmaxf((v.w - mean) * rstd, 0.f);
        base[i] = v;
    }
}

// ============================================================================
// K2b: transpose feat4 (channels 128..639 of g_cv1) into [n][b][hw][c]
// ============================================================================
__global__ void k_transpose()
{
    __shared__ float t[32][33];
    const int n   = blockIdx.z;
    const int c0  = blockIdx.y * 32;    // 0..511 relative to feat4
    const int hw0 = blockIdx.x * 32;
    const int tx = threadIdx.x, ty = threadIdx.y;   // 32 x 8
    const float* src = g_cv1 + ((size_t)n * C5 + BC + c0) * HW + hw0;
#pragma unroll
    for (int r = 0; r < 4; ++r)
        t[ty + r * 8][tx] = src[(size_t)(ty + r * 8) * HW + tx];
    __syncthreads();
    const int b   = c0 >> 7;
    const int cc0 = c0 & 127;
    float* dst = g_f4t + (((size_t)n * 4 + b) * HW + hw0) * BC + cc0;
#pragma unroll
    for (int r = 0; r < 4; ++r)
        dst[(size_t)(ty + r * 8) * BC + tx] = t[tx][ty + r * 8];
}

// ============================================================================
// K3: BorderAlign. 4 pixels per block; params precomputed to smem; each thread
// handles 4 channels (float4 gathers) for one pixel.
// ============================================================================
struct SampP { int o00, o01, o10, o11; float w00, w01, w10, w11; };

__global__ __launch_bounds__(128) void k_border(const float* __restrict__ boxes)
{
    __shared__ SampP sp[4][44];
    const int blk = blockIdx.x;         // pixel quad
    const int t  = threadIdx.x;

    for (int s = t; s < 176; s += 128) {
        const int pix = s / 44, q = s - pix * 44;
        const int b = q / 11, i = q - b * 11;
        const int P = blk * 4 + pix;
        const int n = P / HW, hw = P - n * HW;
        const float4 bx = *(const float4*)(boxes + ((size_t)n * HW + hw) * 4);
        const float bw = (bx.z - bx.x) * 0.1f, bh = (bx.w - bx.y) * 0.1f;
        const float sx = (b == 3) ? bx.z : bx.x;
        const float sy = (b == 2) ? bx.w : bx.y;
        const float dx = (b == 0 || b == 2) ? bw : 0.f;
        const float dy = (b == 1 || b == 3) ? bh : 0.f;
        const float x = sx + dx * (float)i;
        const float y = sy + dy * (float)i;
        const bool valid = (x >= -1.f) && (x <= 96.f) && (y >= -1.f) && (y <= 96.f);
        const float xc = fminf(fmaxf(x, 0.f), 95.f);
        const float yc = fminf(fmaxf(y, 0.f), 95.f);
        int x0 = (int)floorf(xc); if (x0 > 95) x0 = 95;
        int y0 = (int)floorf(yc); if (y0 > 95) y0 = 95;
        const int x1i = x0 + 1 > 95 ? 95 : x0 + 1;
        const int y1i = y0 + 1 > 95 ? 95 : y0 + 1;
        const float lx = (x0 >= 95) ? 0.f : (xc - (float)x0);
        const float ly = (y0 >= 95) ? 0.f : (yc - (float)y0);
        const float hx = 1.f - lx, hy = 1.f - ly;
        const float sv = valid ? 1.f : 0.f;
        SampP p;
        p.o00 = (y0  * 96 + x0 ) * BC;
        p.o01 = (y0  * 96 + x1i) * BC;
        p.o10 = (y1i * 96 + x0 ) * BC;
        p.o11 = (y1i * 96 + x1i) * BC;
        p.w00 = hy * hx * sv;
        p.w01 = hy * lx * sv;
        p.w10 = ly * hx * sv;
        p.w11 = ly * lx * sv;
        sp[pix][q] = p;
    }
    __syncthreads();

    const int half = t >> 5;            // pixel 0..3
    const int ch   = (t & 31) * 4;      // channel quad
    const int P = blk * 4 + half;
    const int n = P / HW, hw = P - n * HW;
    const float* ftn = g_f4t + (size_t)n * 4 * HW * BC + ch;
    float4 o[4];
#pragma unroll
    for (int b = 0; b < 4; ++b) {
        const float* fb = ftn + b * (HW * BC);
        float m0 = -3.4e38f, m1 = -3.4e38f, m2 = -3.4e38f, m3 = -3.4e38f;
#pragma unroll
        for (int i = 0; i < 11; ++i) {
            const SampP p = sp[half][b * 11 + i];
            const float4 v00 = *(const float4*)(fb + p.o00);
            const float4 v01 = *(const float4*)(fb + p.o01);
            const float4 v10 = *(const float4*)(fb + p.o10);
            const float4 v11 = *(const float4*)(fb + p.o11);
            float a0 = p.w00 * v00.x;
            a0 = fmaf(p.w01, v01.x, a0);
            a0 = fmaf(p.w10, v10.x, a0);
            a0 = fmaf(p.w11, v11.x, a0);
            float a1 = p.w00 * v00.y;
            a1 = fmaf(p.w01, v01.y, a1);
            a1 = fmaf(p.w10, v10.y, a1);
            a1 = fmaf(p.w11, v11.y, a1);
            float a2 = p.w00 * v00.z;
            a2 = fmaf(p.w01, v01.z, a2);
            a2 = fmaf(p.w10, v10.z, a2);
            a2 = fmaf(p.w11, v11.z, a2);
            float a3 = p.w00 * v00.w;
            a3 = fmaf(p.w01, v01.w, a3);
            a3 = fmaf(p.w10, v10.w, a3);
            a3 = fmaf(p.w11, v11.w, a3);
            m0 = fmaxf(m0, a0);
            m1 = fmaxf(m1, a1);
            m2 = fmaxf(m2, a2);
            m3 = fmaxf(m3, a3);
        }
        o[b].x = m0; o[b].y = m1; o[b].z = m2; o[b].w = m3;
    }
    float* base = g_ltrb + (size_t)n * C4 * HW;
    float4 r0; r0.x = o[0].x; r0.y = o[1].x; r0.z = o[2].x; r0.w = o[3].x;
    float4 r1; r1.x = o[0].y; r1.y = o[1].y; r1.z = o[2].y; r1.w = o[3].y;
    float4 r2; r2.x = o[0].z; r2.y = o[1].z; r2.z = o[2].z; r2.w = o[3].z;
    float4 r3; r3.x = o[0].w; r3.y = o[1].w; r3.z = o[2].w; r3.w = o[3].w;
    *(float4*)(base + ((size_t)(ch    ) * HW + hw) * 4) = r0;
    *(float4*)(base + ((size_t)(ch + 1) * HW + hw) * 4) = r1;
    *(float4*)(base + ((size_t)(ch + 2) * HW + hw) * 4) = r2;
    *(float4*)(base + ((size_t)(ch + 3) * HW + hw) * 4) = r3;
}

// ============================================================================
// K4: conv3x3 (feat4 -> 640ch) implicit GEMM [640,4608]x[4608,HW], tf32 mma.
// 4 warps, warp tile 64x64.
// ============================================================================
__global__ __launch_bounds__(128) void k_mask(const float* __restrict__ w_mask,
                                              const float* __restrict__ b_mask)
{
    __shared__ uint2 As2[128 * APITCH];
    __shared__ uint2 Bs2[16 * BPITCH];
    const int c0  = blockIdx.y * 128;
    const int p0  = blockIdx.x * 128;
    const int n   = p0 / HW;
    const int hw0 = p0 - n * HW;
    const float* F = g_cv1 + ((size_t)n * C5 + BC) * HW;   // feat4 (post IN+ReLU)
    const int tid  = threadIdx.x;          // 0..127
    const int lane = tid & 31;
    const int wid  = tid >> 5;             // 0..3
    const int warp_m = wid & 1;
    const int warp_n = wid >> 1;
    const int lr = lane >> 2;
    const int lq = lane & 3;

    const int am  = tid >> 4;              // 0..7
    const int app = tid & 15;
    const int aklo = ((app >> 2) << 3) + (app & 3);
    const int bcol = tid;                  // 0..127
    const int phh0 = (hw0 + bcol) / 96;
    const int pww0 = (hw0 + bcol) - phh0 * 96;

    auto gB = [&](int kk) -> float {
        int ci = kk / 9;
        int tap = kk - ci * 9;
        int dy = tap / 3 - 1;
        int dx = tap - (tap / 3) * 3 - 1;
        int hh = phh0 + dy, ww = pww0 + dx;
        float v = 0.f;
        if ((unsigned)hh < 96u && (unsigned)ww < 96u)
            v = F[(size_t)ci * HW + hh * 96 + ww];
        return v;
    };

    float acc[4][8][4];
#pragma unroll
    for (int mt = 0; mt < 4; ++mt)
#pragma unroll
        for (int nt = 0; nt < 8; ++nt)
#pragma unroll
            for (int r = 0; r < 4; ++r) acc[mt][nt][r] = 0.f;

    float2 rA[16], rB[16];
#pragma unroll
    for (int j = 0; j < 16; ++j) {
        const float* W = w_mask + (size_t)(c0 + am + 8 * j) * KMASK;
        rA[j].x = W[aklo];
        rA[j].y = W[aklo + 4];
    }
#pragma unroll
    for (int pr = 0; pr < 16; ++pr) {
        int klo = ((pr >> 2) << 3) + (pr & 3);
        rB[pr].x = gB(klo);
        rB[pr].y = gB(klo + 4);
    }

    const int NT = KMASK / 32;   // 144
    for (int kt = 0; kt < NT; ++kt) {
#pragma unroll
        for (int j = 0; j < 16; ++j) {
            uint2 v; v.x = to_tf32(rA[j].x); v.y = to_tf32(rA[j].y);
            As2[(am + 8 * j) * APITCH + app] = v;
        }
#pragma unroll
        for (int pr = 0; pr < 16; ++pr) {
            uint2 v; v.x = to_tf32(rB[pr].x); v.y = to_tf32(rB[pr].y);
            Bs2[pr * BPITCH + bcol] = v;
        }
        __syncthreads();
        if (kt + 1 < NT) {
            const int k0n = (kt + 1) * 32;
#pragma unroll
            for (int j = 0; j < 16; ++j) {
                const float* W = w_mask + (size_t)(c0 + am + 8 * j) * KMASK + k0n;
                rA[j].x = W[aklo];
                rA[j].y = W[aklo + 4];
            }
#pragma unroll
            for (int pr = 0; pr < 16; ++pr) {
                int klo = k0n + ((pr >> 2) << 3) + (pr & 3);
                rB[pr].x = gB(klo);
                rB[pr].y = gB(klo + 4);
            }
        }
        gemm_tile64(As2, Bs2, acc, warp_m, warp_n, lr, lq);
        __syncthreads();
    }

#pragma unroll
    for (int mt = 0; mt < 4; ++mt) {
        int c_lo = c0 + warp_m * 64 + mt * 16 + lr;
        int c_hi = c_lo + 8;
        float bias_lo = b_mask[c_lo];
        float bias_hi = b_mask[c_hi];
#pragma unroll
        for (int nt = 0; nt < 8; ++nt) {
            int p = hw0 + warp_n * 64 + nt * 8 + 2 * lq;
            float v0 = acc[mt][nt][0] + bias_lo;
            float v1 = acc[mt][nt][1] + bias_lo;
            float v2 = acc[mt][nt][2] + bias_hi;
            float v3 = acc[mt][nt][3] + bias_hi;
            float2 lo, hi;
            lo.x = 1.f / (1.f + __expf(-v0));
            lo.y = 1.f / (1.f + __expf(-v1));
            hi.x = 1.f / (1.f + __expf(-v2));
            hi.y = 1.f / (1.f + __expf(-v3));
            *(float2*)(g_mask + ((size_t)n * C5 + c_lo) * HW + p) = lo;
            *(float2*)(g_mask + ((size_t)n * C5 + c_hi) * HW + p) = hi;
        }
    }
}

// ============================================================================
// K5: final conv1x1 [256,640] on (align*mask), tf32 mma, 4 warps 64x64, ReLU.
// ============================================================================
__global__ __launch_bounds__(128) void k_final(const float* __restrict__ w_border,
    const float* __restrict__ b_border, float* __restrict__ out)
{
    __shared__ uint2 As2[128 * APITCH];
    __shared__ uint2 Bs2[16 * BPITCH];
    const int c0  = blockIdx.y * 128;
    const int p0  = blockIdx.x * 128;
    const int n   = p0 / HW;
    const int hw0 = p0 - n * HW;
    const int tid  = threadIdx.x;          // 0..127
    const int lane = tid & 31;
    const int wid  = tid >> 5;
    const int warp_m = wid & 1;
    const int warp_n = wid >> 1;
    const int lr = lane >> 2;
    const int lq = lane & 3;

    const int am  = tid >> 4;
    const int app = tid & 15;
    const int aklo = ((app >> 2) << 3) + (app & 3);
    const int bcol = tid;

    const float* ltrb_n = g_ltrb + (size_t)n * C4 * HW + hw0 + bcol;
    const float* fms_n  = g_cv1  + (size_t)n * C5 * HW + hw0 + bcol;  // ch0..127 = fm_short
    const float* mask_n = g_mask + (size_t)n * C5 * HW + hw0 + bcol;

    auto loadB = [&](int kk) -> float {
        float a = (kk < C4) ? ltrb_n[(size_t)kk * HW]
                            : fms_n[(size_t)(kk - C4) * HW];
        return a * mask_n[(size_t)kk * HW];
    };

    float acc[4][8][4];
#pragma unroll
    for (int mt = 0; mt < 4; ++mt)
#pragma unroll
        for (int nt = 0; nt < 8; ++nt)
#pragma unroll
            for (int r = 0; r < 4; ++r) acc[mt][nt][r] = 0.f;

    float2 rA[16], rB[16];
#pragma unroll
    for (int j = 0; j < 16; ++j) {
        const float* W = w_border + (size_t)(c0 + am + 8 * j) * C5;
        rA[j].x = W[aklo];
        rA[j].y = W[aklo + 4];
    }
#pragma unroll
    for (int pr = 0; pr < 16; ++pr) {
        int klo = ((pr >> 2) << 3) + (pr & 3);
        rB[pr].x = loadB(klo);
        rB[pr].y = loadB(klo + 4);
    }

    const int NT = C5 / 32;
    for (int kt = 0; kt < NT; ++kt) {
#pragma unroll
        for (int j = 0; j < 16; ++j) {
            uint2 v; v.x = to_tf32(rA[j].x); v.y = to_tf32(rA[j].y);
            As2[(am + 8 * j) * APITCH + app] = v;
        }
#pragma unroll
        for (int pr = 0; pr < 16; ++pr) {
            uint2 v; v.x = to_tf32(rB[pr].x); v.y = to_tf32(rB[pr].y);
            Bs2[pr * BPITCH + bcol] = v;
        }
        __syncthreads();
        if (kt + 1 < NT) {
            int k0 = (kt + 1) * 32;
#pragma unroll
            for (int j = 0; j < 16; ++j) {
                const float* W = w_border + (size_t)(c0 + am + 8 * j) * C5 + k0;
                rA[j].x = W[aklo];
                rA[j].y = W[aklo + 4];
            }
#pragma unroll
            for (int pr = 0; pr < 16; ++pr) {
                int klo = k0 + ((pr >> 2) << 3) + (pr & 3);
                rB[pr].x = loadB(klo);
                rB[pr].y = loadB(klo + 4);
            }
        }
        gemm_tile64(As2, Bs2, acc, warp_m, warp_n, lr, lq);
        __syncthreads();
    }

#pragma unroll
    for (int mt = 0; mt < 4; ++mt) {
        int c_lo = c0 + warp_m * 64 + mt * 16 + lr;
        int c_hi = c_lo + 8;
        float bias_lo = b_border[c_lo];
        float bias_hi = b_border[c_hi];
#pragma unroll
        for (int nt = 0; nt < 8; ++nt) {
            int p = hw0 + warp_n * 64 + nt * 8 + 2 * lq;
            float2 lo, hi;
            lo.x = fmaxf(acc[mt][nt][0] + bias_lo, 0.f);
            lo.y = fmaxf(acc[mt][nt][1] + bias_lo, 0.f);
            hi.x = fmaxf(acc[mt][nt][2] + bias_hi, 0.f);
            hi.y = fmaxf(acc[mt][nt][3] + bias_hi, 0.f);
            *(float2*)(out + ((size_t)n * COUT + c_lo) * HW + p) = lo;
            *(float2*)(out + ((size_t)n * COUT + c_hi) * HW + p) = hi;
        }
    }
}

// ============================================================================
extern "C" void kernel_launch(void* const* d_in, const int* in_sizes, int n_in,
                              void* d_out, int out_size)
{
    const float* feature  = (const float*)d_in[0];
    const float* boxes    = (const float*)d_in[1];
    // d_in[2] = wh (unused by forward)
    const float* w_cur    = (const float*)d_in[3];
    const float* b_cur    = (const float*)d_in[4];
    const float* w_ltrb   = (const float*)d_in[5];
    const float* b_ltrb   = (const float*)d_in[6];
    const float* w_mask   = (const float*)d_in[7];
    const float* b_mask   = (const float*)d_in[8];
    const float* w_border = (const float*)d_in[9];
    const float* b_border = (const float*)d_in[10];
    float* out = (float*)d_out;

    // Side stream + events for capture-safe fork-join (host objects, created once).
    static cudaStream_t s1 = nullptr;
    static cudaEvent_t evA = nullptr, evB = nullptr;
    if (!s1) {
        cudaStreamCreateWithFlags(&s1, cudaStreamNonBlocking);
        cudaEventCreateWithFlags(&evA, cudaEventDisableTiming);
        cudaEventCreateWithFlags(&evB, cudaEventDisableTiming);
    }

    // main (capture) stream: conv1 -> inorm
    k_conv1<<<dim3(144, 5), 128>>>(feature, w_cur, b_cur, w_ltrb, b_ltrb);
    k_inorm<<<NB * C5, 256>>>();
    cudaEventRecord(evA, 0);

    // fork: transpose + border on side stream, concurrent with k_mask below
    cudaStreamWaitEvent(s1, evA, 0);
    k_transpose<<<dim3(288, 16, NB), dim3(32, 8), 0, s1>>>();
    k_border<<<NB * HW / 4, 128, 0, s1>>>(boxes);
    cudaEventRecord(evB, s1);

    // main stream: mask (needs only post-IN g_cv1)
    k_mask<<<dim3(144, 5), 128>>>(w_mask, b_mask);

    // join: final needs g_ltrb (side stream) + g_mask (main stream)
    cudaStreamWaitEvent(0, evB, 0);
    k_final<<<dim3(144, 2), 128>>>(w_border, b_border, out);
}

// round 16
// speedup vs baseline: 1.6170x; 1.2093x over previous
#include <cuda_runtime.h>
#include <cuda_fp16.h>
#include <math.h>
#include <stdint.h>

#define NB   2
#define CIN  256
#define Hh   96
#define Ww   96
#define HW   9216
#define BC   128
#define C4   512
#define C5   640
#define COUT 256
#define KMASK 4608   // 512*9

#define APITCH 20    // uint2 per A row (16 used + 4 pad); 20 % 16 == 4 -> conflict-free
#define BPITCH 132   // uint2 per B pair-row; 132 % 16 == 4 -> conflict-free

// ---- scratch (static device arrays; no allocation) ----
__device__ float g_cv1[(size_t)NB*C5*HW];      // conv1x1 out: ch 0..127 = cur, 128..639 = ltrb (post-IN in place)
__device__ float g_f4t[(size_t)NB*4*HW*BC];    // feat4 transposed: [n][border][hw][c]
__device__ float g_ltrb[(size_t)NB*C4*HW];     // border-align output in the reshaped [n][512][HW] layout
__device__ float g_mask[(size_t)NB*C5*HW];     // sigmoid(conv3x3)

__device__ __forceinline__ uint32_t pack_h2(float lo, float hi) {
    __half2 h = __floats2half2_rn(lo, hi);
    return *(uint32_t*)&h;
}

__device__ __forceinline__ void mma_f16(float* c, const uint32_t* a, const uint32_t* b) {
    asm volatile(
        "mma.sync.aligned.m16n8k16.row.col.f32.f16.f16.f32 "
        "{%0,%1,%2,%3}, {%4,%5,%6,%7}, {%8,%9}, {%0,%1,%2,%3};"
        : "+f"(c[0]), "+f"(c[1]), "+f"(c[2]), "+f"(c[3])
        : "r"(a[0]), "r"(a[1]), "r"(a[2]), "r"(a[3]), "r"(b[0]), "r"(b[1]));
}

// 4-warp tile compute over a 64-K tile of fp16 pairs.
// As2[m][ks*4+lq] = {h2(A[m][16ks+2lq],A[..+1]), h2(A[m][16ks+8+2lq],A[..+1])}
// Bs2[ks*4+lq][col] = {h2(B[16ks+2lq][col],B[+1]), h2(B[16ks+8+2lq][col],B[+1])}
__device__ __forceinline__ void gemm_tile64h(const uint2* As2, const uint2* Bs2,
    float acc[4][8][4], int warp_m, int warp_n, int lr, int lq)
{
#pragma unroll
    for (int ks = 0; ks < 4; ++ks) {
        const int kp = ks * 4 + lq;
        uint32_t afr[4][4], bfr[8][2];
#pragma unroll
        for (int mt = 0; mt < 4; ++mt) {
            int row = warp_m * 64 + mt * 16 + lr;
            uint2 alo = As2[row * APITCH + kp];
            uint2 ahi = As2[(row + 8) * APITCH + kp];
            afr[mt][0] = alo.x; afr[mt][1] = ahi.x;
            afr[mt][2] = alo.y; afr[mt][3] = ahi.y;
        }
#pragma unroll
        for (int nt = 0; nt < 8; ++nt) {
            int col = warp_n * 64 + nt * 8 + lr;
            uint2 b = Bs2[kp * BPITCH + col];
            bfr[nt][0] = b.x; bfr[nt][1] = b.y;
        }
#pragma unroll
        for (int mt = 0; mt < 4; ++mt)
#pragma unroll
            for (int nt = 0; nt < 8; ++nt)
                mma_f16(acc[mt][nt], afr[mt], bfr[nt]);
    }
}

// ============================================================================
// K1: fused conv1x1 (cur||ltrb) = GEMM [640,256]x[256,HW] + bias, fp16 mma.
// ============================================================================
__global__ __launch_bounds__(128, 2) void k_conv1(const float* __restrict__ feat,
    const float* __restrict__ w_cur, const float* __restrict__ b_cur,
    const float* __restrict__ w_ltrb, const float* __restrict__ b_ltrb)
{
    __shared__ uint2 As2[128 * APITCH];
    __shared__ uint2 Bs2[16 * BPITCH];
    const int c0  = blockIdx.y * 128;
    const int p0  = blockIdx.x * 128;
    const int n   = p0 / HW;
    const int hw0 = p0 - n * HW;
    const float* X = feat + (size_t)n * CIN * HW + hw0;
    const int tid  = threadIdx.x;
    const int lane = tid & 31;
    const int wid  = tid >> 5;
    const int warp_m = wid & 1;
    const int warp_n = wid >> 1;
    const int lr = lane >> 2;
    const int lq = lane & 3;

    const int am  = tid >> 4;              // 0..7; rows am+8j, j<16
    const int app = tid & 15;              // slot = ks*4+lq
    const int akb = 16 * (app >> 2) + 2 * (app & 3);   // k base for this slot
    const int bcol = tid;

    float acc[4][8][4];
#pragma unroll
    for (int mt = 0; mt < 4; ++mt)
#pragma unroll
        for (int nt = 0; nt < 8; ++nt)
#pragma unroll
            for (int r = 0; r < 4; ++r) acc[mt][nt][r] = 0.f;

    uint2 rA[16], rB[16];
    auto ldA = [&](int j, int k0) -> uint2 {
        int c = c0 + am + 8 * j;
        const float* W = ((c < BC) ? (w_cur + c * CIN) : (w_ltrb + (c - BC) * CIN)) + k0 + akb;
        float2 p0 = *(const float2*)(W);
        float2 p1 = *(const float2*)(W + 8);
        uint2 v; v.x = pack_h2(p0.x, p0.y); v.y = pack_h2(p1.x, p1.y);
        return v;
    };
    auto ldB = [&](int pr, int k0) -> uint2 {
        int kb = k0 + 16 * (pr >> 2) + 2 * (pr & 3);
        uint2 v;
        v.x = pack_h2(X[(size_t)kb * HW + bcol],       X[(size_t)(kb + 1) * HW + bcol]);
        v.y = pack_h2(X[(size_t)(kb + 8) * HW + bcol], X[(size_t)(kb + 9) * HW + bcol]);
        return v;
    };

#pragma unroll
    for (int j = 0; j < 16; ++j) rA[j] = ldA(j, 0);
#pragma unroll
    for (int pr = 0; pr < 16; ++pr) rB[pr] = ldB(pr, 0);

    const int NT = CIN / 64;   // 4
    for (int kt = 0; kt < NT; ++kt) {
#pragma unroll
        for (int j = 0; j < 16; ++j) As2[(am + 8 * j) * APITCH + app] = rA[j];
#pragma unroll
        for (int pr = 0; pr < 16; ++pr) Bs2[pr * BPITCH + bcol] = rB[pr];
        __syncthreads();
        if (kt + 1 < NT) {
            int k0 = (kt + 1) * 64;
#pragma unroll
            for (int j = 0; j < 16; ++j) rA[j] = ldA(j, k0);
#pragma unroll
            for (int pr = 0; pr < 16; ++pr) rB[pr] = ldB(pr, k0);
        }
        gemm_tile64h(As2, Bs2, acc, warp_m, warp_n, lr, lq);
        __syncthreads();
    }

#pragma unroll
    for (int mt = 0; mt < 4; ++mt) {
        int c_lo = c0 + warp_m * 64 + mt * 16 + lr;
        int c_hi = c_lo + 8;
        float bias_lo = (c_lo < BC) ? b_cur[c_lo] : b_ltrb[c_lo - BC];
        float bias_hi = (c_hi < BC) ? b_cur[c_hi] : b_ltrb[c_hi - BC];
#pragma unroll
        for (int nt = 0; nt < 8; ++nt) {
            int p = hw0 + warp_n * 64 + nt * 8 + 2 * lq;
            float2 lo, hi;
            lo.x = acc[mt][nt][0] + bias_lo;
            lo.y = acc[mt][nt][1] + bias_lo;
            hi.x = acc[mt][nt][2] + bias_hi;
            hi.y = acc[mt][nt][3] + bias_hi;
            *(float2*)(g_cv1 + ((size_t)n * C5 + c_lo) * HW + p) = lo;
            *(float2*)(g_cv1 + ((size_t)n * C5 + c_hi) * HW + p) = hi;
        }
    }
}

// ============================================================================
// K2: instance norm (biased var, eps=1e-5) + ReLU, in place. One block per (n,c).
// ============================================================================
__global__ __launch_bounds__(256) void k_inorm()
{
    const int nc = blockIdx.x;          // n*C5 + c
    float4* base = (float4*)(g_cv1 + (size_t)nc * HW);
    const int tid = threadIdx.x;
    float s = 0.f, q = 0.f;
#pragma unroll
    for (int i = tid; i < HW / 4; i += 256) {
        float4 v = base[i];
        s += v.x + v.y + v.z + v.w;
        q += v.x * v.x + v.y * v.y + v.z * v.z + v.w * v.w;
    }
    __shared__ float ss[256], qq[256];
    ss[tid] = s; qq[tid] = q;
    __syncthreads();
    for (int off = 128; off > 0; off >>= 1) {
        if (tid < off) { ss[tid] += ss[tid + off]; qq[tid] += qq[tid + off]; }
        __syncthreads();
    }
    const float mean = ss[0] * (1.f / HW);
    const float var  = qq[0] * (1.f / HW) - mean * mean;
    const float rstd = rsqrtf(var + 1e-5f);
#pragma unroll
    for (int i = tid; i < HW / 4; i += 256) {
        float4 v = base[i];
        v.x = fmaxf((v.x - mean) * rstd, 0.f);
        v.y = fmaxf((v.y - mean) * rstd, 0.f);
        v.z = fmaxf((v.z - mean) * rstd, 0.f);
        v.w = fmaxf((v.w - mean) * rstd, 0.f);
        base[i] = v;
    }
}

// ============================================================================
// K2b: transpose feat4 (channels 128..639 of g_cv1) into [n][b][hw][c]
// ============================================================================
__global__ void k_transpose()
{
    __shared__ float t[32][33];
    const int n   = blockIdx.z;
    const int c0  = blockIdx.y * 32;    // 0..511 relative to feat4
    const int hw0 = blockIdx.x * 32;
    const int tx = threadIdx.x, ty = threadIdx.y;   // 32 x 8
    const float* src = g_cv1 + ((size_t)n * C5 + BC + c0) * HW + hw0;
#pragma unroll
    for (int r = 0; r < 4; ++r)
        t[ty + r * 8][tx] = src[(size_t)(ty + r * 8) * HW + tx];
    __syncthreads();
    const int b   = c0 >> 7;
    const int cc0 = c0 & 127;
    float* dst = g_f4t + (((size_t)n * 4 + b) * HW + hw0) * BC + cc0;
#pragma unroll
    for (int r = 0; r < 4; ++r)
        dst[(size_t)(ty + r * 8) * BC + tx] = t[tx][ty + r * 8];
}

// ============================================================================
// K3: BorderAlign. 4 pixels per block; params precomputed to smem; each thread
// handles 4 channels (float4 gathers) for one pixel.
// ============================================================================
struct SampP { int o00, o01, o10, o11; float w00, w01, w10, w11; };

__global__ __launch_bounds__(128) void k_border(const float* __restrict__ boxes)
{
    __shared__ SampP sp[4][44];
    const int blk = blockIdx.x;         // pixel quad
    const int t  = threadIdx.x;

    for (int s = t; s < 176; s += 128) {
        const int pix = s / 44, q = s - pix * 44;
        const int b = q / 11, i = q - b * 11;
        const int P = blk * 4 + pix;
        const int n = P / HW, hw = P - n * HW;
        const float4 bx = *(const float4*)(boxes + ((size_t)n * HW + hw) * 4);
        const float bw = (bx.z - bx.x) * 0.1f, bh = (bx.w - bx.y) * 0.1f;
        const float sx = (b == 3) ? bx.z : bx.x;
        const float sy = (b == 2) ? bx.w : bx.y;
        const float dx = (b == 0 || b == 2) ? bw : 0.f;
        const float dy = (b == 1 || b == 3) ? bh : 0.f;
        const float x = sx + dx * (float)i;
        const float y = sy + dy * (float)i;
        const bool valid = (x >= -1.f) && (x <= 96.f) && (y >= -1.f) && (y <= 96.f);
        const float xc = fminf(fmaxf(x, 0.f), 95.f);
        const float yc = fminf(fmaxf(y, 0.f), 95.f);
        int x0 = (int)floorf(xc); if (x0 > 95) x0 = 95;
        int y0 = (int)floorf(yc); if (y0 > 95) y0 = 95;
        const int x1i = x0 + 1 > 95 ? 95 : x0 + 1;
        const int y1i = y0 + 1 > 95 ? 95 : y0 + 1;
        const float lx = (x0 >= 95) ? 0.f : (xc - (float)x0);
        const float ly = (y0 >= 95) ? 0.f : (yc - (float)y0);
        const float hx = 1.f - lx, hy = 1.f - ly;
        const float sv = valid ? 1.f : 0.f;
        SampP p;
        p.o00 = (y0  * 96 + x0 ) * BC;
        p.o01 = (y0  * 96 + x1i) * BC;
        p.o10 = (y1i * 96 + x0 ) * BC;
        p.o11 = (y1i * 96 + x1i) * BC;
        p.w00 = hy * hx * sv;
        p.w01 = hy * lx * sv;
        p.w10 = ly * hx * sv;
        p.w11 = ly * lx * sv;
        sp[pix][q] = p;
    }
    __syncthreads();

    const int half = t >> 5;            // pixel 0..3
    const int ch   = (t & 31) * 4;      // channel quad
    const int P = blk * 4 + half;
    const int n = P / HW, hw = P - n * HW;
    const float* ftn = g_f4t + (size_t)n * 4 * HW * BC + ch;
    float4 o[4];
#pragma unroll
    for (int b = 0; b < 4; ++b) {
        const float* fb = ftn + b * (HW * BC);
        float m0 = -3.4e38f, m1 = -3.4e38f, m2 = -3.4e38f, m3 = -3.4e38f;
#pragma unroll
        for (int i = 0; i < 11; ++i) {
            const SampP p = sp[half][b * 11 + i];
            const float4 v00 = *(const float4*)(fb + p.o00);
            const float4 v01 = *(const float4*)(fb + p.o01);
            const float4 v10 = *(const float4*)(fb + p.o10);
            const float4 v11 = *(const float4*)(fb + p.o11);
            float a0 = p.w00 * v00.x;
            a0 = fmaf(p.w01, v01.x, a0);
            a0 = fmaf(p.w10, v10.x, a0);
            a0 = fmaf(p.w11, v11.x, a0);
            float a1 = p.w00 * v00.y;
            a1 = fmaf(p.w01, v01.y, a1);
            a1 = fmaf(p.w10, v10.y, a1);
            a1 = fmaf(p.w11, v11.y, a1);
            float a2 = p.w00 * v00.z;
            a2 = fmaf(p.w01, v01.z, a2);
            a2 = fmaf(p.w10, v10.z, a2);
            a2 = fmaf(p.w11, v11.z, a2);
            float a3 = p.w00 * v00.w;
            a3 = fmaf(p.w01, v01.w, a3);
            a3 = fmaf(p.w10, v10.w, a3);
            a3 = fmaf(p.w11, v11.w, a3);
            m0 = fmaxf(m0, a0);
            m1 = fmaxf(m1, a1);
            m2 = fmaxf(m2, a2);
            m3 = fmaxf(m3, a3);
        }
        o[b].x = m0; o[b].y = m1; o[b].z = m2; o[b].w = m3;
    }
    float* base = g_ltrb + (size_t)n * C4 * HW;
    float4 r0; r0.x = o[0].x; r0.y = o[1].x; r0.z = o[2].x; r0.w = o[3].x;
    float4 r1; r1.x = o[0].y; r1.y = o[1].y; r1.z = o[2].y; r1.w = o[3].y;
    float4 r2; r2.x = o[0].z; r2.y = o[1].z; r2.z = o[2].z; r2.w = o[3].z;
    float4 r3; r3.x = o[0].w; r3.y = o[1].w; r3.z = o[2].w; r3.w = o[3].w;
    *(float4*)(base + ((size_t)(ch    ) * HW + hw) * 4) = r0;
    *(float4*)(base + ((size_t)(ch + 1) * HW + hw) * 4) = r1;
    *(float4*)(base + ((size_t)(ch + 2) * HW + hw) * 4) = r2;
    *(float4*)(base + ((size_t)(ch + 3) * HW + hw) * 4) = r3;
}

// ============================================================================
// K4: conv3x3 (feat4 -> 640ch) implicit GEMM [640,4608]x[4608,HW], fp16 mma.
// ============================================================================
__global__ __launch_bounds__(128, 2) void k_mask(const float* __restrict__ w_mask,
                                                 const float* __restrict__ b_mask)
{
    __shared__ uint2 As2[128 * APITCH];
    __shared__ uint2 Bs2[16 * BPITCH];
    const int c0  = blockIdx.y * 128;
    const int p0  = blockIdx.x * 128;
    const int n   = p0 / HW;
    const int hw0 = p0 - n * HW;
    const float* F = g_cv1 + ((size_t)n * C5 + BC) * HW;   // feat4 (post IN+ReLU)
    const int tid  = threadIdx.x;
    const int lane = tid & 31;
    const int wid  = tid >> 5;
    const int warp_m = wid & 1;
    const int warp_n = wid >> 1;
    const int lr = lane >> 2;
    const int lq = lane & 3;

    const int am  = tid >> 4;
    const int app = tid & 15;
    const int akb = 16 * (app >> 2) + 2 * (app & 3);
    const int bcol = tid;
    const int phh0 = (hw0 + bcol) / 96;
    const int pww0 = (hw0 + bcol) - phh0 * 96;

    auto gB = [&](int kk) -> float {
        int ci = kk / 9;
        int tap = kk - ci * 9;
        int dy = tap / 3 - 1;
        int dx = tap - (tap / 3) * 3 - 1;
        int hh = phh0 + dy, ww = pww0 + dx;
        float v = 0.f;
        if ((unsigned)hh < 96u && (unsigned)ww < 96u)
            v = F[(size_t)ci * HW + hh * 96 + ww];
        return v;
    };

    float acc[4][8][4];
#pragma unroll
    for (int mt = 0; mt < 4; ++mt)
#pragma unroll
        for (int nt = 0; nt < 8; ++nt)
#pragma unroll
            for (int r = 0; r < 4; ++r) acc[mt][nt][r] = 0.f;

    uint2 rA[16], rB[16];
    auto ldA = [&](int j, int k0) -> uint2 {
        const float* W = w_mask + (size_t)(c0 + am + 8 * j) * KMASK + k0 + akb;
        float2 p0 = *(const float2*)(W);
        float2 p1 = *(const float2*)(W + 8);
        uint2 v; v.x = pack_h2(p0.x, p0.y); v.y = pack_h2(p1.x, p1.y);
        return v;
    };
    auto ldB = [&](int pr, int k0) -> uint2 {
        int kb = k0 + 16 * (pr >> 2) + 2 * (pr & 3);
        uint2 v;
        v.x = pack_h2(gB(kb),     gB(kb + 1));
        v.y = pack_h2(gB(kb + 8), gB(kb + 9));
        return v;
    };

#pragma unroll
    for (int j = 0; j < 16; ++j) rA[j] = ldA(j, 0);
#pragma unroll
    for (int pr = 0; pr < 16; ++pr) rB[pr] = ldB(pr, 0);

    const int NT = KMASK / 64;   // 72
    for (int kt = 0; kt < NT; ++kt) {
#pragma unroll
        for (int j = 0; j < 16; ++j) As2[(am + 8 * j) * APITCH + app] = rA[j];
#pragma unroll
        for (int pr = 0; pr < 16; ++pr) Bs2[pr * BPITCH + bcol] = rB[pr];
        __syncthreads();
        if (kt + 1 < NT) {
            int k0 = (kt + 1) * 64;
#pragma unroll
            for (int j = 0; j < 16; ++j) rA[j] = ldA(j, k0);
#pragma unroll
            for (int pr = 0; pr < 16; ++pr) rB[pr] = ldB(pr, k0);
        }
        gemm_tile64h(As2, Bs2, acc, warp_m, warp_n, lr, lq);
        __syncthreads();
    }

#pragma unroll
    for (int mt = 0; mt < 4; ++mt) {
        int c_lo = c0 + warp_m * 64 + mt * 16 + lr;
        int c_hi = c_lo + 8;
        float bias_lo = b_mask[c_lo];
        float bias_hi = b_mask[c_hi];
#pragma unroll
        for (int nt = 0; nt < 8; ++nt) {
            int p = hw0 + warp_n * 64 + nt * 8 + 2 * lq;
            float v0 = acc[mt][nt][0] + bias_lo;
            float v1 = acc[mt][nt][1] + bias_lo;
            float v2 = acc[mt][nt][2] + bias_hi;
            float v3 = acc[mt][nt][3] + bias_hi;
            float2 lo, hi;
            lo.x = 1.f / (1.f + __expf(-v0));
            lo.y = 1.f / (1.f + __expf(-v1));
            hi.x = 1.f / (1.f + __expf(-v2));
            hi.y = 1.f / (1.f + __expf(-v3));
            *(float2*)(g_mask + ((size_t)n * C5 + c_lo) * HW + p) = lo;
            *(float2*)(g_mask + ((size_t)n * C5 + c_hi) * HW + p) = hi;
        }
    }
}

// ============================================================================
// K5: final conv1x1 [256,640] on (align*mask), fp16 mma, ReLU.
// ============================================================================
__global__ __launch_bounds__(128, 2) void k_final(const float* __restrict__ w_border,
    const float* __restrict__ b_border, float* __restrict__ out)
{
    __shared__ uint2 As2[128 * APITCH];
    __shared__ uint2 Bs2[16 * BPITCH];
    const int c0  = blockIdx.y * 128;
    const int p0  = blockIdx.x * 128;
    const int n   = p0 / HW;
    const int hw0 = p0 - n * HW;
    const int tid  = threadIdx.x;
    const int lane = tid & 31;
    const int wid  = tid >> 5;
    const int warp_m = wid & 1;
    const int warp_n = wid >> 1;
    const int lr = lane >> 2;
    const int lq = lane & 3;

    const int am  = tid >> 4;
    const int app = tid & 15;
    const int akb = 16 * (app >> 2) + 2 * (app & 3);
    const int bcol = tid;

    const float* ltrb_n = g_ltrb + (size_t)n * C4 * HW + hw0 + bcol;
    const float* fms_n  = g_cv1  + (size_t)n * C5 * HW + hw0 + bcol;  // ch0..127 = fm_short
    const float* mask_n = g_mask + (size_t)n * C5 * HW + hw0 + bcol;

    auto loadB = [&](int kk) -> float {
        float a = (kk < C4) ? ltrb_n[(size_t)kk * HW]
                            : fms_n[(size_t)(kk - C4) * HW];
        return a * mask_n[(size_t)kk * HW];
    };

    float acc[4][8][4];
#pragma unroll
    for (int mt = 0; mt < 4; ++mt)
#pragma unroll
        for (int nt = 0; nt < 8; ++nt)
#pragma unroll
            for (int r = 0; r < 4; ++r) acc[mt][nt][r] = 0.f;

    uint2 rA[16], rB[16];
    auto ldA = [&](int j, int k0) -> uint2 {
        const float* W = w_border + (size_t)(c0 + am + 8 * j) * C5 + k0 + akb;
        float2 p0 = *(const float2*)(W);
        float2 p1 = *(const float2*)(W + 8);
        uint2 v; v.x = pack_h2(p0.x, p0.y); v.y = pack_h2(p1.x, p1.y);
        return v;
    };
    auto ldB = [&](int pr, int k0) -> uint2 {
        int kb = k0 + 16 * (pr >> 2) + 2 * (pr & 3);
        uint2 v;
        v.x = pack_h2(loadB(kb),     loadB(kb + 1));
        v.y = pack_h2(loadB(kb + 8), loadB(kb + 9));
        return v;
    };

#pragma unroll
    for (int j = 0; j < 16; ++j) rA[j] = ldA(j, 0);
#pragma unroll
    for (int pr = 0; pr < 16; ++pr) rB[pr] = ldB(pr, 0);

    const int NT = C5 / 64;   // 10
    for (int kt = 0; kt < NT; ++kt) {
#pragma unroll
        for (int j = 0; j < 16; ++j) As2[(am + 8 * j) * APITCH + app] = rA[j];
#pragma unroll
        for (int pr = 0; pr < 16; ++pr) Bs2[pr * BPITCH + bcol] = rB[pr];
        __syncthreads();
        if (kt + 1 < NT) {
            int k0 = (kt + 1) * 64;
#pragma unroll
            for (int j = 0; j < 16; ++j) rA[j] = ldA(j, k0);
#pragma unroll
            for (int pr = 0; pr < 16; ++pr) rB[pr] = ldB(pr, k0);
        }
        gemm_tile64h(As2, Bs2, acc, warp_m, warp_n, lr, lq);
        __syncthreads();
    }

#pragma unroll
    for (int mt = 0; mt < 4; ++mt) {
        int c_lo = c0 + warp_m * 64 + mt * 16 + lr;
        int c_hi = c_lo + 8;
        float bias_lo = b_border[c_lo];
        float bias_hi = b_border[c_hi];
#pragma unroll
        for (int nt = 0; nt < 8; ++nt) {
            int p = hw0 + warp_n * 64 + nt * 8 + 2 * lq;
            float2 lo, hi;
            lo.x = fmaxf(acc[mt][nt][0] + bias_lo, 0.f);
            lo.y = fmaxf(acc[mt][nt][1] + bias_lo, 0.f);
            hi.x = fmaxf(acc[mt][nt][2] + bias_hi, 0.f);
            hi.y = fmaxf(acc[mt][nt][3] + bias_hi, 0.f);
            *(float2*)(out + ((size_t)n * COUT + c_lo) * HW + p) = lo;
            *(float2*)(out + ((size_t)n * COUT + c_hi) * HW + p) = hi;
        }
    }
}

// ============================================================================
extern "C" void kernel_launch(void* const* d_in, const int* in_sizes, int n_in,
                              void* d_out, int out_size)
{
    const float* feature  = (const float*)d_in[0];
    const float* boxes    = (const float*)d_in[1];
    // d_in[2] = wh (unused by forward)
    const float* w_cur    = (const float*)d_in[3];
    const float* b_cur    = (const float*)d_in[4];
    const float* w_ltrb   = (const float*)d_in[5];
    const float* b_ltrb   = (const float*)d_in[6];
    const float* w_mask   = (const float*)d_in[7];
    const float* b_mask   = (const float*)d_in[8];
    const float* w_border = (const float*)d_in[9];
    const float* b_border = (const float*)d_in[10];
    float* out = (float*)d_out;

    // Side stream + events for capture-safe fork-join (host objects, created once).
    static cudaStream_t s1 = nullptr;
    static cudaEvent_t evA = nullptr, evB = nullptr;
    if (!s1) {
        cudaStreamCreateWithFlags(&s1, cudaStreamNonBlocking);
        cudaEventCreateWithFlags(&evA, cudaEventDisableTiming);
        cudaEventCreateWithFlags(&evB, cudaEventDisableTiming);
    }

    // main (capture) stream: conv1 -> inorm
    k_conv1<<<dim3(144, 5), 128>>>(feature, w_cur, b_cur, w_ltrb, b_ltrb);
    k_inorm<<<NB * C5, 256>>>();
    cudaEventRecord(evA, 0);

    // fork: transpose + border on side stream, concurrent with k_mask below
    cudaStreamWaitEvent(s1, evA, 0);
    k_transpose<<<dim3(288, 16, NB), dim3(32, 8), 0, s1>>>();
    k_border<<<NB * HW / 4, 128, 0, s1>>>(boxes);
    cudaEventRecord(evB, s1);

    // main stream: mask (needs only post-IN g_cv1)
    k_mask<<<dim3(144, 5), 128>>>(w_mask, b_mask);

    // join: final needs g_ltrb (side stream) + g_mask (main stream)
    cudaStreamWaitEvent(0, evB, 0);
    k_final<<<dim3(144, 2), 128>>>(w_border, b_border, out);
}